// round 14
// baseline (speedup 1.0000x reference)
#include <cuda_runtime.h>
#include <cuda_bf16.h>
#include <math.h>
#include <stdint.h>

#define N_CELLS 4096
#define IN_DIM 1024
#define HID 1024
#define OUT_DIM 1024
#define NT 8
#define NF 8
#define GIN 1025
#define G3 3072

typedef __nv_bfloat16 bf16;
typedef __nv_bfloat162 bf162;

// ---------------- scratch (device globals) ----------------
__device__ bf16 g_hid_h[N_CELLS * HID],   g_hid_l[N_CELLS * HID];
__device__ bf16 g_wih_h[G3 * 1024],       g_wih_l[G3 * 1024];
__device__ bf16 g_whh_h[G3 * 1024],       g_whh_l[G3 * 1024];
__device__ bf16 g_b1_h[256 * 1024],       g_b1_l[256 * 1024];
__device__ bf16 g_wc2_h[1024 * 256],      g_wc2_l[1024 * 256];
__device__ bf16 g_w2t_h[256 * 1024],      g_w2t_l[256 * 1024];
__device__ bf16 g_mcat_h[G3 * 256],       g_mcat_l[G3 * 256];
__device__ bf16 g_a1g1_h[N_CELLS * 256],  g_a1g1_l[N_CELLS * 256];
__device__ bf16 g_gq_h[256 * 256],        g_gq_l[256 * 256];   // G = Wcat2^T Wcat2
__device__ float g_u2[256];                                     // 2 * Wcat2^T bconst
__device__ float g_bsq[1];
__device__ float g_gi[N_CELLS * G3];
__device__ float g_gh[N_CELLS * G3];
__device__ float g_nh[N_CELLS * HID];
__device__ float g_tension[N_CELLS];
__device__ float g_energy[N_CELLS];
__device__ int   g_votes[N_CELLS];
__device__ float g_bias1[256];
__device__ float g_bconst[1024];
__device__ float g_vih[G3];
__device__ float g_wt[G3];
__device__ float g_counts[NT];
__device__ float g_cft[NF * NT];
__device__ float g_fsum_ft[NF * NT * HID];
__device__ float g_sums[NT * HID];
__device__ float g_fsums[NF * HID];
__device__ float g_glob[HID];
__device__ float g_w[N_CELLS];
__device__ float g_wa[256];
__device__ float g_combined[OUT_DIM];

// ---------------- asm helpers ----------------
__device__ __forceinline__ uint32_t smem_u32(const void* p) {
    uint32_t a;
    asm("{ .reg .u64 t; cvta.to.shared.u64 t, %1; cvt.u32.u64 %0, t; }" : "=r"(a) : "l"(p));
    return a;
}
__device__ __forceinline__ void cpa16(uint32_t s, const void* g) {
    asm volatile("cp.async.cg.shared.global [%0], [%1], 16;" :: "r"(s), "l"(g));
}
__device__ __forceinline__ void cp_commit() {
    asm volatile("cp.async.commit_group;" ::: "memory");
}
template <int N>
__device__ __forceinline__ void cp_wait() {
    asm volatile("cp.async.wait_group %0;" :: "n"(N) : "memory");
}
__device__ __forceinline__ void ldsm4(uint32_t& r0, uint32_t& r1, uint32_t& r2, uint32_t& r3,
                                      uint32_t a) {
    asm volatile("ldmatrix.sync.aligned.m8n8.x4.shared.b16 {%0,%1,%2,%3}, [%4];"
                 : "=r"(r0), "=r"(r1), "=r"(r2), "=r"(r3) : "r"(a));
}
__device__ __forceinline__ void mma16816(float c[4], const uint32_t a[4], const uint32_t b[2])
{
    asm("mma.sync.aligned.m16n8k16.row.col.f32.bf16.bf16.f32 "
        "{%0,%1,%2,%3}, {%4,%5,%6,%7}, {%8,%9}, {%0,%1,%2,%3};"
        : "+f"(c[0]), "+f"(c[1]), "+f"(c[2]), "+f"(c[3])
        : "r"(a[0]), "r"(a[1]), "r"(a[2]), "r"(a[3]), "r"(b[0]), "r"(b[1]));
}
__device__ __forceinline__ void split_bf16(float x, bf16& hi, bf16& lo)
{
    hi = __float2bfloat16_rn(x);
    lo = __float2bfloat16_rn(x - __bfloat162float(hi));
}
__device__ __forceinline__ void store_pair(bf16* H, bf16* L, size_t idx, float2 v)
{
    bf16 hx, lx, hy, ly;
    split_bf16(v.x, hx, lx);
    split_bf16(v.y, hy, ly);
    bf162 hp; hp.x = hx; hp.y = hy;
    bf162 lp; lp.x = lx; lp.y = ly;
    *(bf162*)(H + idx) = hp;
    *(bf162*)(L + idx) = lp;
}
__device__ __forceinline__ float2 load_pair(const bf16* H, const bf16* L, size_t idx)
{
    bf162 hp = *(const bf162*)(H + idx);
    bf162 lp = *(const bf162*)(L + idx);
    float2 r;
    r.x = __bfloat162float(hp.x) + __bfloat162float(lp.x);
    r.y = __bfloat162float(hp.y) + __bfloat162float(lp.y);
    return r;
}
__device__ __forceinline__ float wred(float v)
{
    v += __shfl_xor_sync(0xffffffffu, v, 16);
    v += __shfl_xor_sync(0xffffffffu, v, 8);
    v += __shfl_xor_sync(0xffffffffu, v, 4);
    v += __shfl_xor_sync(0xffffffffu, v, 2);
    v += __shfl_xor_sync(0xffffffffu, v, 1);
    return v;
}

// ---- epilogue modes: 0 fp32 write, 1 bf16 split+relu, 2 sumsq, 3 bf16 split,
//                      4 quadform-dot (dot (acc+bias) with A1G1 -> tension) ----
template <int MODE, int MI>
__device__ __forceinline__ void epilogue(
    float (*acc)[8][4], int m0, int nb0,
    bf16* __restrict__ Chi, bf16* __restrict__ Clo, int ldcb,
    float* __restrict__ Cf, int ldcf,
    const float* __restrict__ bias,
    int wm, int wn, int g, int tg)
{
#pragma unroll
    for (int mi = 0; mi < MI; mi++) {
        int row0 = m0 + wm * (16 * MI) + mi * 16 + g;
        float p0 = 0.f, p1 = 0.f;
#pragma unroll
        for (int ni = 0; ni < 8; ni++) {
            int lc = wn * 64 + ni * 8 + tg * 2;
            float b0 = bias ? bias[lc] : 0.f;
            float b1 = bias ? bias[lc + 1] : 0.f;
            float v0 = acc[mi][ni][0] + b0;
            float v1 = acc[mi][ni][1] + b1;
            float v2 = acc[mi][ni][2] + b0;
            float v3 = acc[mi][ni][3] + b1;
            if (MODE == 1) {
                v0 = fmaxf(v0, 0.f); v1 = fmaxf(v1, 0.f);
                v2 = fmaxf(v2, 0.f); v3 = fmaxf(v3, 0.f);
            }
            if (MODE == 2) { p0 += v0 * v0 + v1 * v1; p1 += v2 * v2 + v3 * v3; }
            if (MODE == 4) {
                float2 a0 = load_pair(Chi, Clo, (size_t)row0 * ldcb + nb0 + lc);
                float2 a1 = load_pair(Chi, Clo, (size_t)(row0 + 8) * ldcb + nb0 + lc);
                p0 += v0 * a0.x + v1 * a0.y;
                p1 += v2 * a1.x + v3 * a1.y;
            }
            if (MODE == 1 || MODE == 3) {
                float2 a; a.x = v0; a.y = v1;
                float2 b; b.x = v2; b.y = v3;
                store_pair(Chi, Clo, (size_t)row0 * ldcb + nb0 + lc, a);
                store_pair(Chi, Clo, (size_t)(row0 + 8) * ldcb + nb0 + lc, b);
            }
            if (MODE == 0) {
                float2 q0; q0.x = v0; q0.y = v1;
                float2 q1; q1.x = v2; q1.y = v3;
                *(float2*)(Cf + (size_t)row0 * ldcf + nb0 + lc) = q0;
                *(float2*)(Cf + (size_t)(row0 + 8) * ldcf + nb0 + lc) = q1;
            }
        }
        if (MODE == 2 || MODE == 4) {
            p0 += __shfl_xor_sync(0xffffffffu, p0, 1);
            p0 += __shfl_xor_sync(0xffffffffu, p0, 2);
            p1 += __shfl_xor_sync(0xffffffffu, p1, 1);
            p1 += __shfl_xor_sync(0xffffffffu, p1, 2);
            if (tg == 0) {
                atomicAdd(&g_tension[row0], p0);
                atomicAdd(&g_tension[row0 + 8], p1);
            }
        }
    }
}

// =============== merged dual-region bf16 split GEMM ===============
template <int MI, int NSPLIT, int MODE1, int MODE2>
__global__ void __launch_bounds__(256) gemm2(
    const bf16* __restrict__ Ahi, const bf16* __restrict__ Alo, int lda,
    const bf16* __restrict__ B1h, const bf16* __restrict__ B1l,
    const bf16* __restrict__ B2h, const bf16* __restrict__ B2l,
    bf16* __restrict__ Chi, bf16* __restrict__ Clo, int ldcb,
    float* __restrict__ C1, int ldc1,
    float* __restrict__ C2, int ldc2,
    int K,
    const float* __restrict__ bias1, const float* __restrict__ bias2)
{
    constexpr int TM = 64 * MI;
    constexpr int ABYTES = TM * 128;
    constexpr int BBYTES = 128 * 128;
    constexpr int STAGE = 2 * ABYTES + 2 * BBYTES;

    extern __shared__ __align__(1024) char smem[];
    const uint32_t sb = smem_u32(smem);
    const int tid = threadIdx.x;
    const int wid = tid >> 5, lane = tid & 31;
    const int wm = wid & 3, wn = wid >> 2;
    const int g = lane >> 2, tg = lane & 3;
    const int m0 = blockIdx.y * TM, n0 = blockIdx.x * 128;
    const int nc = K >> 6;

    const bool r1 = (n0 < NSPLIT);
    const int nb0 = r1 ? n0 : n0 - NSPLIT;
    const bf16* __restrict__ Bh = (r1 ? B1h : B2h) + (size_t)nb0 * K;
    const bf16* __restrict__ Bl = (r1 ? B1l : B2l) + (size_t)nb0 * K;
    const float* bias = r1 ? (bias1 ? bias1 + nb0 : nullptr)
                           : (bias2 ? bias2 + nb0 : nullptr);

    float acc[MI][8][4];
#pragma unroll
    for (int mi = 0; mi < MI; mi++)
#pragma unroll
        for (int ni = 0; ni < 8; ni++)
#pragma unroll
            for (int q = 0; q < 4; q++) acc[mi][ni][q] = 0.f;

    auto load_stage = [&](int c, int b) {
        const uint32_t s0 = sb + b * STAGE;
        const int k0 = c << 6;
#pragma unroll
        for (int it = 0; it < TM * 8 / 256; it++) {
            int idx = tid + it * 256;
            int row = idx >> 3, ch = idx & 7;
            uint32_t so = (uint32_t)(row << 7) + (uint32_t)((ch ^ (row & 7)) << 4);
            size_t go = (size_t)(m0 + row) * lda + k0 + ch * 8;
            cpa16(s0 + so, Ahi + go);
            cpa16(s0 + ABYTES + so, Alo + go);
        }
#pragma unroll
        for (int it = 0; it < 4; it++) {
            int idx = tid + it * 256;
            int row = idx >> 3, ch = idx & 7;
            uint32_t so = (uint32_t)(row << 7) + (uint32_t)((ch ^ (row & 7)) << 4);
            size_t go = (size_t)row * K + k0 + ch * 8;
            cpa16(s0 + 2 * ABYTES + so, Bh + go);
            cpa16(s0 + 2 * ABYTES + BBYTES + so, Bl + go);
        }
        cp_commit();
    };

    const int j = lane >> 3;
    const int arow_b = wm * (16 * MI) + (j & 1) * 8 + (lane & 7);
    const int brow_b = wn * 64 + (j >> 1) * 8 + (lane & 7);

    load_stage(0, 0);

    for (int c = 0; c < nc; c++) {
        cp_wait<0>();
        __syncthreads();

        const uint32_t sA = sb + (c & 1) * STAGE;
        const uint32_t sB = sA + 2 * ABYTES;

#pragma unroll
        for (int ks = 0; ks < 4; ks++) {
            uint32_t bh[8][2], bl[8][2];
            uint32_t ah[MI][4], al[MI][4];
            const int achunk = ks * 2 + (j >> 1);
            const int bchunk = ks * 2 + (j & 1);
#pragma unroll
            for (int nb = 0; nb < 4; nb++) {
                int r = brow_b + nb * 16;
                uint32_t off = (uint32_t)(r << 7) + (uint32_t)((bchunk ^ (r & 7)) << 4);
                uint32_t t0, t1, t2, t3;
                ldsm4(t0, t1, t2, t3, sB + off);
                bh[2 * nb][0] = t0; bh[2 * nb][1] = t1;
                bh[2 * nb + 1][0] = t2; bh[2 * nb + 1][1] = t3;
                ldsm4(t0, t1, t2, t3, sB + BBYTES + off);
                bl[2 * nb][0] = t0; bl[2 * nb][1] = t1;
                bl[2 * nb + 1][0] = t2; bl[2 * nb + 1][1] = t3;
            }
#pragma unroll
            for (int mi = 0; mi < MI; mi++) {
                int r = arow_b + mi * 16;
                uint32_t off = (uint32_t)(r << 7) + (uint32_t)((achunk ^ (r & 7)) << 4);
                ldsm4(ah[mi][0], ah[mi][1], ah[mi][2], ah[mi][3], sA + off);
                ldsm4(al[mi][0], al[mi][1], al[mi][2], al[mi][3], sA + ABYTES + off);
            }
#pragma unroll
            for (int mi = 0; mi < MI; mi++)
#pragma unroll
                for (int ni = 0; ni < 8; ni++)
                    mma16816(acc[mi][ni], ah[mi], bh[ni]);
#pragma unroll
            for (int mi = 0; mi < MI; mi++)
#pragma unroll
                for (int ni = 0; ni < 8; ni++)
                    mma16816(acc[mi][ni], ah[mi], bl[ni]);
#pragma unroll
            for (int mi = 0; mi < MI; mi++)
#pragma unroll
                for (int ni = 0; ni < 8; ni++)
                    mma16816(acc[mi][ni], al[mi], bh[ni]);
            if (ks == 0 && c + 1 < nc) load_stage(c + 1, (c + 1) & 1);
        }
    }

    if (r1) epilogue<MODE1, MI>(acc, m0, nb0, Chi, Clo, ldcb, C1, ldc1, bias, wm, wn, g, tg);
    else    epilogue<MODE2, MI>(acc, m0, nb0, Chi, Clo, ldcb, C2, ldc2, bias, wm, wn, g, tg);
}

// ---------------- prep (float4-vectorized critical path) ----------------
__global__ void k_prep_crit(const float* __restrict__ hiddens,
                            const float* __restrict__ W_hh,
                            const float* __restrict__ Wa1, const float* __restrict__ Wg1)
{
    const long S0 = 1048576L, S1 = 786432L, S2 = 65536L;   // float4 counts
    long i = (long)blockIdx.x * 256 + threadIdx.x;
    if (i < S0) {
        float4 v = ((const float4*)hiddens)[i];
        float2 a; a.x = v.x; a.y = v.y;
        float2 b; b.x = v.z; b.y = v.w;
        store_pair(g_hid_h, g_hid_l, (size_t)(4 * i), a);
        store_pair(g_hid_h, g_hid_l, (size_t)(4 * i) + 2, b);
    } else if (i < S0 + S1) {
        long k4 = i - S0;
        float4 v = ((const float4*)W_hh)[k4];
        float2 a; a.x = v.x; a.y = v.y;
        float2 b; b.x = v.z; b.y = v.w;
        store_pair(g_whh_h, g_whh_l, (size_t)(4 * k4), a);
        store_pair(g_whh_h, g_whh_l, (size_t)(4 * k4) + 2, b);
    } else if (i < S0 + S1 + S2) {
        long k = 4 * (i - S0 - S1);
        int r = (int)(k >> 10), c = (int)(k & 1023);
        const float* src = (r < 128) ? (Wa1 + (size_t)r * 2048 + 1024 + c)
                                     : (Wg1 + (size_t)(r - 128) * 2048 + 1024 + c);
        float4 v = *(const float4*)src;
        float2 a; a.x = v.x; a.y = v.y;
        float2 b; b.x = v.z; b.y = v.w;
        store_pair(g_b1_h, g_b1_l, (size_t)k, a);
        store_pair(g_b1_h, g_b1_l, (size_t)k + 2, b);
    }
}

__global__ void k_prep_side(const float* __restrict__ W_ih,
                            const float* __restrict__ Wa2, const float* __restrict__ Wg2)
{
    const long SW = 1572864L;
    long i = (long)blockIdx.x * 256 + threadIdx.x;
    if (i < SW) {
        long k = 2 * i;
        int r = (int)(k >> 10), c = (int)(k & 1023);
        const float* src = W_ih + (size_t)r * GIN + c;
        float2 v; v.x = src[0]; v.y = src[1];
        store_pair(g_wih_h, g_wih_l, (size_t)k, v);
    } else if (i < SW + 131072L) {
        long k = i - SW;
        int jr = (int)(k >> 7), m = (int)(k & 127);
        float va = Wa2[k], vg = -Wg2[k];
        bf16 h, l;
        split_bf16(va, h, l);
        g_wc2_h[jr * 256 + m] = h;          g_wc2_l[jr * 256 + m] = l;
        g_w2t_h[m * 1024 + jr] = h;         g_w2t_l[m * 1024 + jr] = l;
        split_bf16(vg, h, l);
        g_wc2_h[jr * 256 + 128 + m] = h;    g_wc2_l[jr * 256 + 128 + m] = l;
        g_w2t_h[(128 + m) * 1024 + jr] = h; g_w2t_l[(128 + m) * 1024 + jr] = l;
    }
}

// u2 = 2 * Wcat2^T bconst ; bsq = ||bconst||^2   (1 block, 256 threads)
__global__ void k_u(const float* __restrict__ Wa2, const float* __restrict__ Wg2)
{
    int m = threadIdx.x;
    bool neg = m >= 128;
    const float* W = neg ? Wg2 : Wa2;
    int mm = m & 127;
    float u = 0.f;
    for (int jj = 0; jj < 1024; jj++)
        u += g_bconst[jj] * W[jj * 128 + mm];
    g_u2[m] = neg ? -2.f * u : 2.f * u;
    float s = 0.f;
    for (int jj = m; jj < 1024; jj += 256) s += g_bconst[jj] * g_bconst[jj];
    __shared__ float sh[256];
    sh[m] = s; __syncthreads();
    for (int o = 128; o > 0; o >>= 1) {
        if (m < o) sh[m] += sh[m + o];
        __syncthreads();
    }
    if (m == 0) g_bsq[0] = sh[0];
}

__global__ void k_zero(const float* __restrict__ ba2, const float* __restrict__ bg2)
{
    int i = blockIdx.x * 256 + threadIdx.x;
    if (i < NT) g_counts[i] = 0.f;
    if (i < NF * NT) g_cft[i] = 0.f;
    if (i < NF * NT * HID) g_fsum_ft[i] = 0.f;
    if (i < 256) g_wa[i] = 0.f;
    if (i < N_CELLS) g_tension[i] = 0.f;
    if (i < 1024) g_bconst[i] = ba2[i] - bg2[i];
}

__global__ void k_bias1(const float* __restrict__ Wa1, const float* __restrict__ ba1,
                        const float* __restrict__ Wg1, const float* __restrict__ bg1,
                        const float* __restrict__ x)
{
    int b = blockIdx.x * 8 + (threadIdx.x >> 5);
    int lane = threadIdx.x & 31;
    const float* row = (b < 128) ? (Wa1 + (size_t)b * 2048) : (Wg1 + (size_t)(b - 128) * 2048);
    float s = 0.f;
    for (int jj = lane; jj < 1024; jj += 32) s += row[jj] * x[jj];
    s = wred(s);
    if (lane == 0)
        g_bias1[b] = s + ((b < 128) ? ba1[b] : bg1[b - 128]);
}

__global__ void k_vih(const float* __restrict__ W_ih, const float* __restrict__ b_ih)
{
    int k = blockIdx.x * 8 + (threadIdx.x >> 5);
    int lane = threadIdx.x & 31;
    const float* row = W_ih + (size_t)k * GIN;
    float s = 0.f;
    for (int jj = lane; jj < 1024; jj += 32) s += row[jj] * g_bconst[jj];
    s = wred(s);
    if (lane == 0) { g_vih[k] = s + b_ih[k]; g_wt[k] = row[1024]; }
}

__global__ void k_vote(const float* __restrict__ infl, const float* __restrict__ op,
                       const float* __restrict__ noise)
{
    int row = blockIdx.x;
    int tid = threadIdx.x;
    int lane = tid & 31, wid = tid >> 5;
    float acc[NT];
#pragma unroll
    for (int t = 0; t < NT; t++) acc[t] = 0.f;
    const float4* ir4 = (const float4*)(infl + (size_t)row * N_CELLS);
    for (int c4 = tid; c4 < N_CELLS / 4; c4 += 256) {
        float4 w4 = ir4[c4];
        float ws[4] = {w4.x, w4.y, w4.z, w4.w};
#pragma unroll
        for (int q = 0; q < 4; q++) {
            if (ws[q] != 0.f) {
                const float4* o4 = (const float4*)(op + (size_t)(4 * c4 + q) * NT);
                float4 a = o4[0], b = o4[1];
                acc[0] += ws[q] * a.x; acc[1] += ws[q] * a.y;
                acc[2] += ws[q] * a.z; acc[3] += ws[q] * a.w;
                acc[4] += ws[q] * b.x; acc[5] += ws[q] * b.y;
                acc[6] += ws[q] * b.z; acc[7] += ws[q] * b.w;
            }
        }
    }
    __shared__ float sh[8][NT];
#pragma unroll
    for (int t = 0; t < NT; t++) {
        float v = wred(acc[t]);
        if (lane == 0) sh[wid][t] = v;
    }
    __syncthreads();
    if (tid == 0) {
        float v[NT]; float sum = 0.f;
#pragma unroll
        for (int t = 0; t < NT; t++) {
            float s = 0.f;
#pragma unroll
            for (int w = 0; w < 8; w++) s += sh[w][t];
            float u = 0.7f * op[row * NT + t] + 0.3f * s + 0.01f * noise[row * NT + t];
            u = fmaxf(u, 0.01f);
            v[t] = u; sum += u;
        }
        float inv = 1.f / sum;
        int am = 0; float mx = v[0] * inv;
#pragma unroll
        for (int t = 1; t < NT; t++) {
            float u = v[t] * inv;
            if (u > mx) { mx = u; am = t; }
        }
        g_votes[row] = am;
        g_energy[row] = mx;
        atomicAdd(&g_counts[am], 1.f);
        atomicAdd(&g_cft[(row >> 9) * NT + am], 1.f);
    }
}

// float4 GRU with fused per-(faction,topic) segment sums; tension += bsq
__global__ void k_gru(const float* __restrict__ hiddens)
{
    int i = blockIdx.x;
    float scale = 0.9f + 0.2f * g_energy[i];
    float t = (g_tension[i] + g_bsq[0]) * (1.f / 1024.f);
    int vt = g_votes[i];
    int fa = i >> 9;
    const float4* gi = (const float4*)(g_gi + (size_t)i * G3);
    const float4* gh = (const float4*)(g_gh + (size_t)i * G3);
    const float4* wt = (const float4*)g_wt;
    const float4* hd = (const float4*)(hiddens + (size_t)i * 1024);
    float4* nh = (float4*)(g_nh + (size_t)i * HID);
    int j4 = threadIdx.x;
    float4 gir = gi[j4],        ghr = gh[j4];
    float4 giz = gi[j4 + 256],  ghz = gh[j4 + 256];
    float4 gin = gi[j4 + 512],  ghn = gh[j4 + 512];
    float4 wtr = wt[j4], wtz = wt[j4 + 256], wtn = wt[j4 + 512];
    float4 h = hd[j4];
    float4 o;
    {
        float r = 1.f / (1.f + expf(-(gir.x + t * wtr.x + ghr.x)));
        float z = 1.f / (1.f + expf(-(giz.x + t * wtz.x + ghz.x)));
        float n = tanhf(gin.x + t * wtn.x + r * ghn.x);
        o.x = fminf(fmaxf(((1.f - z) * n + z * h.x) * scale, -10.f), 10.f);
    }
    {
        float r = 1.f / (1.f + expf(-(gir.y + t * wtr.y + ghr.y)));
        float z = 1.f / (1.f + expf(-(giz.y + t * wtz.y + ghz.y)));
        float n = tanhf(gin.y + t * wtn.y + r * ghn.y);
        o.y = fminf(fmaxf(((1.f - z) * n + z * h.y) * scale, -10.f), 10.f);
    }
    {
        float r = 1.f / (1.f + expf(-(gir.z + t * wtr.z + ghr.z)));
        float z = 1.f / (1.f + expf(-(giz.z + t * wtz.z + ghz.z)));
        float n = tanhf(gin.z + t * wtn.z + r * ghn.z);
        o.z = fminf(fmaxf(((1.f - z) * n + z * h.z) * scale, -10.f), 10.f);
    }
    {
        float r = 1.f / (1.f + expf(-(gir.w + t * wtr.w + ghr.w)));
        float z = 1.f / (1.f + expf(-(giz.w + t * wtz.w + ghz.w)));
        float n = tanhf(gin.w + t * wtn.w + r * ghn.w);
        o.w = fminf(fmaxf(((1.f - z) * n + z * h.w) * scale, -10.f), 10.f);
    }
    nh[j4] = o;
    float* sums = g_fsum_ft + ((size_t)(fa * NT + vt)) * HID + 4 * j4;
    atomicAdd(sums + 0, o.x);
    atomicAdd(sums + 1, o.y);
    atomicAdd(sums + 2, o.z);
    atomicAdd(sums + 3, o.w);
}

__global__ void k_fblend()
{
    int c = blockIdx.x * 256 + threadIdx.x;
    float sums_t[NT];
#pragma unroll
    for (int t = 0; t < NT; t++) {
        float s = 0.f;
#pragma unroll
        for (int f = 0; f < NF; f++)
            s += g_fsum_ft[(size_t)(f * NT + t) * HID + c];
        sums_t[t] = s;
        g_sums[t * HID + c] = s;
    }
    float glob = 0.f;
#pragma unroll
    for (int f = 0; f < NF; f++) {
        float v = 0.f;
#pragma unroll
        for (int t = 0; t < NT; t++) {
            float raw = g_fsum_ft[(size_t)(f * NT + t) * HID + c];
            float cnt = g_counts[t];
            if (cnt >= 2.f)
                v += 0.85f * raw + 0.15f * g_cft[f * NT + t] * (sums_t[t] / fmaxf(cnt, 1.f));
            else
                v += raw;
        }
        g_fsums[f * HID + c] = v;
        glob += v;
    }
    g_glob[c] = glob * (1.f / 4096.f);
}

__global__ void k_final(float* __restrict__ out_nh, const int* __restrict__ step)
{
    int i = blockIdx.x;
    int f = i >> 9;
    int t = g_votes[i];
    float cnt = g_counts[t];
    bool ap = (cnt >= 2.f);
    float invc = 1.f / fmaxf(cnt, 1.f);
    bool dcz = (*step > 5) && ((i & 511) < 128);
    for (int jj = threadIdx.x; jj < HID; jj += 256) {
        float v = g_nh[(size_t)i * HID + jj];
        if (ap) v = 0.85f * v + 0.15f * g_sums[t * HID + jj] * invc;
        float fm = g_fsums[f * HID + jj] * (1.f / 512.f);
        v = 0.85f * v + 0.15f * fm;
        if (dcz) v = 0.85f * v + 0.15f * g_glob[jj];
        out_nh[(size_t)i * HID + jj] = v;
    }
}

__global__ void k_softmax(float* __restrict__ out_avg)
{
    __shared__ float sh[1024];
    int tid = threadIdx.x;
    float bsq = g_bsq[0];
    float t4[4];
    float mx = -1e30f, av = 0.f;
#pragma unroll
    for (int q = 0; q < 4; q++) {
        t4[q] = (g_tension[tid + q * 1024] + bsq) * (1.f / 1024.f);
        mx = fmaxf(mx, t4[q]);
        av += t4[q];
    }
    sh[tid] = mx; __syncthreads();
    for (int o = 512; o > 0; o >>= 1) {
        if (tid < o) sh[tid] = fmaxf(sh[tid], sh[tid + o]);
        __syncthreads();
    }
    float M = sh[0]; __syncthreads();
    float sm = 0.f;
#pragma unroll
    for (int q = 0; q < 4; q++) {
        float e = expf(t4[q] - M);
        g_w[tid + q * 1024] = e;
        sm += e;
    }
    sh[tid] = sm; __syncthreads();
    for (int o = 512; o > 0; o >>= 1) {
        if (tid < o) sh[tid] += sh[tid + o];
        __syncthreads();
    }
    float inv = 1.f / sh[0]; __syncthreads();
#pragma unroll
    for (int q = 0; q < 4; q++) g_w[tid + q * 1024] *= inv;
    sh[tid] = av; __syncthreads();
    for (int o = 512; o > 0; o >>= 1) {
        if (tid < o) sh[tid] += sh[tid + o];
        __syncthreads();
    }
    if (tid == 0) out_avg[0] = sh[0] * (1.f / 4096.f);
}

__global__ void k_wA()
{
    int c = threadIdx.x;
    int r0 = blockIdx.x * 128;
    float acc = 0.f;
    for (int r = r0; r < r0 + 128; r++) {
        float w = g_w[r];
        float v = __bfloat162float(g_a1g1_h[(size_t)r * 256 + c])
                + __bfloat162float(g_a1g1_l[(size_t)r * 256 + c]);
        acc += w * v;
    }
    atomicAdd(&g_wa[c], acc);
}

__global__ void k_comb2()
{
    int jr = blockIdx.x * 8 + (threadIdx.x >> 5);
    int lane = threadIdx.x & 31;
    float s = 0.f;
    for (int m = lane; m < 256; m += 32) {
        float wv = __bfloat162float(g_wc2_h[(size_t)jr * 256 + m])
                 + __bfloat162float(g_wc2_l[(size_t)jr * 256 + m]);
        s += g_wa[m] * wv;
    }
    s = wred(s);
    if (lane == 0) g_combined[jr] = s + g_bconst[jr];
}

__global__ void k_pred(const float* __restrict__ Wo, const float* __restrict__ bo,
                       float* __restrict__ out_pred)
{
    int i = blockIdx.x * 8 + (threadIdx.x >> 5);
    int lane = threadIdx.x & 31;
    const float* row = Wo + (size_t)i * 1024;
    float s = 0.f;
    for (int jj = lane; jj < 1024; jj += 32) s += g_combined[jj] * row[jj];
    s = wred(s);
    if (lane == 0) out_pred[i] = s + bo[i];
}

// ---------------- launch ----------------
template <typename T>
static T* symp(const void* s)
{
    void* p = nullptr;
    cudaGetSymbolAddress(&p, s);
    return (T*)p;
}

#define SMEM_MI1 (2 * (2 * 64 * 128 + 2 * 128 * 128))    // 96 KB
#define SMEM_MI4 (2 * (2 * 256 * 128 + 2 * 128 * 128))   // 192 KB

extern "C" void kernel_launch(void* const* d_in, const int* in_sizes, int n_in,
                              void* d_out, int out_size)
{
    const float* x        = (const float*)d_in[0];
    const float* hiddens  = (const float*)d_in[1];
    const float* opinions = (const float*)d_in[2];
    const float* influence= (const float*)d_in[3];
    const float* noise    = (const float*)d_in[4];
    const float* Wa1 = (const float*)d_in[5];
    const float* ba1 = (const float*)d_in[6];
    const float* Wa2 = (const float*)d_in[7];
    const float* ba2 = (const float*)d_in[8];
    const float* Wg1 = (const float*)d_in[9];
    const float* bg1 = (const float*)d_in[10];
    const float* Wg2 = (const float*)d_in[11];
    const float* bg2 = (const float*)d_in[12];
    const float* W_ih = (const float*)d_in[13];
    const float* b_ih = (const float*)d_in[14];
    const float* W_hh = (const float*)d_in[15];
    const float* b_hh = (const float*)d_in[16];
    const float* Wo  = (const float*)d_in[17];
    const float* bo  = (const float*)d_in[18];
    const int*   step = (const int*)d_in[19];

    float* out = (float*)d_out;
    float* out_pred = out;
    float* out_avg  = out + 1024;
    float* out_nh   = out + 1025;

    bf16* pHidH = symp<bf16>(g_hid_h);  bf16* pHidL = symp<bf16>(g_hid_l);
    bf16* pWihH = symp<bf16>(g_wih_h);  bf16* pWihL = symp<bf16>(g_wih_l);
    bf16* pWhhH = symp<bf16>(g_whh_h);  bf16* pWhhL = symp<bf16>(g_whh_l);
    bf16* pB1H  = symp<bf16>(g_b1_h);   bf16* pB1L  = symp<bf16>(g_b1_l);
    bf16* pWc2H = symp<bf16>(g_wc2_h);  bf16* pWc2L = symp<bf16>(g_wc2_l);
    bf16* pW2TH = symp<bf16>(g_w2t_h);  bf16* pW2TL = symp<bf16>(g_w2t_l);
    bf16* pMcH  = symp<bf16>(g_mcat_h); bf16* pMcL  = symp<bf16>(g_mcat_l);
    bf16* pAgH  = symp<bf16>(g_a1g1_h); bf16* pAgL  = symp<bf16>(g_a1g1_l);
    bf16* pGqH  = symp<bf16>(g_gq_h);   bf16* pGqL  = symp<bf16>(g_gq_l);
    float* pGi  = symp<float>(g_gi);
    float* pGh  = symp<float>(g_gh);
    float* pBias1 = symp<float>(g_bias1);
    float* pVih = symp<float>(g_vih);
    float* pU2  = symp<float>(g_u2);

    static bool init_done = false;
    static bool use_streams = false;
    static cudaStream_t sM = nullptr, sV = nullptr, sG = nullptr;
    static cudaEvent_t ev0 = nullptr, evPC = nullptr, evM = nullptr, evBV = nullptr,
                       evV = nullptr, evG = nullptr, evT = nullptr, evP = nullptr;
    if (!init_done) {
        init_done = true;
        cudaFuncSetAttribute(gemm2<1, 4096, 3, 0>,   // Mcat / Gq
                             cudaFuncAttributeMaxDynamicSharedMemorySize, SMEM_MI1);
        cudaFuncSetAttribute(gemm2<1, 4096, 1, 0>,   // A1G1
                             cudaFuncAttributeMaxDynamicSharedMemorySize, SMEM_MI1);
        cudaFuncSetAttribute(gemm2<4, 4096, 0, 0>,   // gh
                             cudaFuncAttributeMaxDynamicSharedMemorySize, SMEM_MI4);
        cudaFuncSetAttribute(gemm2<4, 3072, 0, 4>,   // gi | quadform-tension
                             cudaFuncAttributeMaxDynamicSharedMemorySize, SMEM_MI4);
        use_streams =
            (cudaStreamCreateWithFlags(&sM, cudaStreamNonBlocking) == cudaSuccess) &&
            (cudaStreamCreateWithFlags(&sV, cudaStreamNonBlocking) == cudaSuccess) &&
            (cudaStreamCreateWithFlags(&sG, cudaStreamNonBlocking) == cudaSuccess) &&
            (cudaEventCreateWithFlags(&ev0, cudaEventDisableTiming) == cudaSuccess) &&
            (cudaEventCreateWithFlags(&evPC, cudaEventDisableTiming) == cudaSuccess) &&
            (cudaEventCreateWithFlags(&evM, cudaEventDisableTiming) == cudaSuccess) &&
            (cudaEventCreateWithFlags(&evBV, cudaEventDisableTiming) == cudaSuccess) &&
            (cudaEventCreateWithFlags(&evV, cudaEventDisableTiming) == cudaSuccess) &&
            (cudaEventCreateWithFlags(&evG, cudaEventDisableTiming) == cudaSuccess) &&
            (cudaEventCreateWithFlags(&evT, cudaEventDisableTiming) == cudaSuccess) &&
            (cudaEventCreateWithFlags(&evP, cudaEventDisableTiming) == cudaSuccess);
    }

    cudaStream_t m = use_streams ? sM : (cudaStream_t)0;
    cudaStream_t vv = use_streams ? sV : (cudaStream_t)0;
    cudaStream_t gg = use_streams ? sG : (cudaStream_t)0;

    k_zero<<<256, 256>>>(ba2, bg2);

    if (use_streams) {
        cudaEventRecord(ev0, 0);
        cudaStreamWaitEvent(vv, ev0, 0);
        cudaStreamWaitEvent(m, ev0, 0);
    }
    k_vote<<<N_CELLS, 256, 0, vv>>>(influence, opinions, noise);
    if (use_streams) cudaEventRecord(evV, vv);

    // side stream: bias1, vih, u/bsq, prep_side, Mcat, Gq
    k_bias1<<<32, 256, 0, m>>>(Wa1, ba1, Wg1, bg1, x);
    k_vih<<<G3 / 8, 256, 0, m>>>(W_ih, b_ih);
    k_u<<<1, 256, 0, m>>>(Wa2, Wg2);
    if (use_streams) cudaEventRecord(evBV, m);
    k_prep_side<<<6656, 256, 0, m>>>(W_ih, Wa2, Wg2);
    gemm2<1, 4096, 3, 0><<<dim3(2, 48), 256, SMEM_MI1, m>>>(
        pWihH, pWihL, 1024,
        pW2TH, pW2TL, nullptr, nullptr,
        pMcH, pMcL, 256,
        nullptr, 0, nullptr, 0,
        1024, nullptr, nullptr);
    // Gq = W2T @ W2T^T (256x256, K=1024)
    gemm2<1, 4096, 3, 0><<<dim3(2, 4), 256, SMEM_MI1, m>>>(
        pW2TH, pW2TL, 1024,
        pW2TH, pW2TL, nullptr, nullptr,
        pGqH, pGqL, 256,
        nullptr, 0, nullptr, 0,
        1024, nullptr, nullptr);
    if (use_streams) cudaEventRecord(evM, m);

    // critical prep on stream 0 (float4)
    k_prep_crit<<<7424, 256>>>(hiddens, W_hh, Wa1, Wg1);
    if (use_streams) cudaEventRecord(evPC, 0);

    // gh GEMM on its own stream
    if (use_streams) cudaStreamWaitEvent(gg, evPC, 0);
    gemm2<4, 4096, 0, 0><<<dim3(24, 16), 256, SMEM_MI4, gg>>>(
        pHidH, pHidL, 1024,
        pWhhH, pWhhL, nullptr, nullptr,
        nullptr, nullptr, 0,
        pGh, G3, nullptr, 0,
        1024, b_hh, nullptr);
    if (use_streams) cudaEventRecord(evG, gg);

    // A1G1 GEMM on stream 0
    if (use_streams) cudaStreamWaitEvent(0, evBV, 0);
    gemm2<1, 4096, 1, 0><<<dim3(2, 64), 256, SMEM_MI1>>>(
        pHidH, pHidL, 1024,
        pB1H, pB1L, nullptr, nullptr,
        pAgH, pAgL, 256,
        nullptr, 0, nullptr, 0,
        1024, pBias1, nullptr);

    // gi | quadform-tension GEMM on stream 0 (N = 3072 + 256, grid 26 x 16)
    if (use_streams) cudaStreamWaitEvent(0, evM, 0);
    gemm2<4, 3072, 0, 4><<<dim3(26, 16), 256, SMEM_MI4>>>(
        pAgH, pAgL, 256,
        pMcH, pMcL, pGqH, pGqL,
        pAgH, pAgL, 256,          // mode-4 reads A1G1 via Chi/Clo
        pGi, G3, nullptr, 0,
        256, pVih, pU2);
    if (use_streams) { cudaEventRecord(evT, 0); cudaStreamWaitEvent(m, evT, 0); }

    // softmax -> pred chain on side stream
    k_softmax<<<1, 1024, 0, m>>>(out_avg);
    k_wA<<<32, 256, 0, m>>>();
    k_comb2<<<128, 256, 0, m>>>();
    k_pred<<<128, 256, 0, m>>>(Wo, bo, out_pred);
    if (use_streams) cudaEventRecord(evP, m);

    // GRU chain
    if (use_streams) { cudaStreamWaitEvent(0, evG, 0); cudaStreamWaitEvent(0, evV, 0); }
    k_gru<<<N_CELLS, 256>>>(hiddens);
    k_fblend<<<4, 256>>>();
    k_final<<<N_CELLS, 256>>>(out_nh, step);

    if (use_streams) cudaStreamWaitEvent(0, evP, 0);
}

// round 15
// speedup vs baseline: 1.1131x; 1.1131x over previous
#include <cuda_runtime.h>
#include <cuda_bf16.h>
#include <math.h>
#include <stdint.h>

#define N_CELLS 4096
#define IN_DIM 1024
#define HID 1024
#define OUT_DIM 1024
#define NT 8
#define NF 8
#define GIN 1025
#define G3 3072

typedef __nv_bfloat16 bf16;
typedef __nv_bfloat162 bf162;

// ---------------- scratch (device globals) ----------------
__device__ bf16 g_hid_h[N_CELLS * HID],   g_hid_l[N_CELLS * HID];
__device__ bf16 g_wih_h[G3 * 1024],       g_wih_l[G3 * 1024];
__device__ bf16 g_whh_h[G3 * 1024],       g_whh_l[G3 * 1024];
__device__ bf16 g_b1_h[256 * 1024],       g_b1_l[256 * 1024];
__device__ bf16 g_wc2_h[1024 * 256],      g_wc2_l[1024 * 256];
__device__ bf16 g_w2t_h[256 * 1024],      g_w2t_l[256 * 1024];
__device__ bf16 g_mcat_h[G3 * 256],       g_mcat_l[G3 * 256];
__device__ bf16 g_a1g1_h[N_CELLS * 256],  g_a1g1_l[N_CELLS * 256];
__device__ float g_gi[N_CELLS * G3];
__device__ float g_gh[N_CELLS * G3];
__device__ float g_nh[N_CELLS * HID];
__device__ float g_tension[N_CELLS];
__device__ float g_energy[N_CELLS];
__device__ int   g_votes[N_CELLS];
__device__ float g_bias1[256];
__device__ float g_bconst[1024];
__device__ float g_vih[G3];
__device__ float g_wt[G3];
__device__ float g_counts[NT];
__device__ float g_cft[NF * NT];
__device__ float g_fsum_ft[NF * NT * HID];
__device__ float g_sums[NT * HID];
__device__ float g_fsums[NF * HID];
__device__ float g_glob[HID];
__device__ float g_w[N_CELLS];
__device__ float g_wa[256];
__device__ float g_combined[OUT_DIM];

// ---------------- asm helpers ----------------
__device__ __forceinline__ uint32_t smem_u32(const void* p) {
    uint32_t a;
    asm("{ .reg .u64 t; cvta.to.shared.u64 t, %1; cvt.u32.u64 %0, t; }" : "=r"(a) : "l"(p));
    return a;
}
__device__ __forceinline__ void cpa16(uint32_t s, const void* g) {
    asm volatile("cp.async.cg.shared.global [%0], [%1], 16;" :: "r"(s), "l"(g));
}
__device__ __forceinline__ void cp_commit() {
    asm volatile("cp.async.commit_group;" ::: "memory");
}
template <int N>
__device__ __forceinline__ void cp_wait() {
    asm volatile("cp.async.wait_group %0;" :: "n"(N) : "memory");
}
__device__ __forceinline__ void ldsm4(uint32_t& r0, uint32_t& r1, uint32_t& r2, uint32_t& r3,
                                      uint32_t a) {
    asm volatile("ldmatrix.sync.aligned.m8n8.x4.shared.b16 {%0,%1,%2,%3}, [%4];"
                 : "=r"(r0), "=r"(r1), "=r"(r2), "=r"(r3) : "r"(a));
}
__device__ __forceinline__ void mma16816(float c[4], const uint32_t a[4], const uint32_t b[2])
{
    asm("mma.sync.aligned.m16n8k16.row.col.f32.bf16.bf16.f32 "
        "{%0,%1,%2,%3}, {%4,%5,%6,%7}, {%8,%9}, {%0,%1,%2,%3};"
        : "+f"(c[0]), "+f"(c[1]), "+f"(c[2]), "+f"(c[3])
        : "r"(a[0]), "r"(a[1]), "r"(a[2]), "r"(a[3]), "r"(b[0]), "r"(b[1]));
}
__device__ __forceinline__ void split_bf16(float x, bf16& hi, bf16& lo)
{
    hi = __float2bfloat16_rn(x);
    lo = __float2bfloat16_rn(x - __bfloat162float(hi));
}
__device__ __forceinline__ void store_pair(bf16* H, bf16* L, size_t idx, float2 v)
{
    bf16 hx, lx, hy, ly;
    split_bf16(v.x, hx, lx);
    split_bf16(v.y, hy, ly);
    bf162 hp; hp.x = hx; hp.y = hy;
    bf162 lp; lp.x = lx; lp.y = ly;
    *(bf162*)(H + idx) = hp;
    *(bf162*)(L + idx) = lp;
}
__device__ __forceinline__ float wred(float v)
{
    v += __shfl_xor_sync(0xffffffffu, v, 16);
    v += __shfl_xor_sync(0xffffffffu, v, 8);
    v += __shfl_xor_sync(0xffffffffu, v, 4);
    v += __shfl_xor_sync(0xffffffffu, v, 2);
    v += __shfl_xor_sync(0xffffffffu, v, 1);
    return v;
}

// ---- epilogue modes: 0 = fp32 write, 1 = bf16 split + relu, 2 = sumsq-only, 3 = bf16 split ----
template <int MODE, int MI>
__device__ __forceinline__ void epilogue(
    float (*acc)[8][4], int m0, int nb0,
    bf16* __restrict__ Chi, bf16* __restrict__ Clo, int ldcb,
    float* __restrict__ Cf, int ldcf,
    const float* __restrict__ bias,
    int wm, int wn, int g, int tg)
{
#pragma unroll
    for (int mi = 0; mi < MI; mi++) {
        int row0 = m0 + wm * (16 * MI) + mi * 16 + g;
        float p0 = 0.f, p1 = 0.f;
#pragma unroll
        for (int ni = 0; ni < 8; ni++) {
            int lc = wn * 64 + ni * 8 + tg * 2;
            float b0 = bias ? bias[lc] : 0.f;
            float b1 = bias ? bias[lc + 1] : 0.f;
            float v0 = acc[mi][ni][0] + b0;
            float v1 = acc[mi][ni][1] + b1;
            float v2 = acc[mi][ni][2] + b0;
            float v3 = acc[mi][ni][3] + b1;
            if (MODE == 1) {
                v0 = fmaxf(v0, 0.f); v1 = fmaxf(v1, 0.f);
                v2 = fmaxf(v2, 0.f); v3 = fmaxf(v3, 0.f);
            }
            if (MODE == 2) { p0 += v0 * v0 + v1 * v1; p1 += v2 * v2 + v3 * v3; }
            if (MODE == 1 || MODE == 3) {
                float2 a; a.x = v0; a.y = v1;
                float2 b; b.x = v2; b.y = v3;
                store_pair(Chi, Clo, (size_t)row0 * ldcb + nb0 + lc, a);
                store_pair(Chi, Clo, (size_t)(row0 + 8) * ldcb + nb0 + lc, b);
            }
            if (MODE == 0) {
                float2 q0; q0.x = v0; q0.y = v1;
                float2 q1; q1.x = v2; q1.y = v3;
                *(float2*)(Cf + (size_t)row0 * ldcf + nb0 + lc) = q0;
                *(float2*)(Cf + (size_t)(row0 + 8) * ldcf + nb0 + lc) = q1;
            }
        }
        if (MODE == 2) {
            p0 += __shfl_xor_sync(0xffffffffu, p0, 1);
            p0 += __shfl_xor_sync(0xffffffffu, p0, 2);
            p1 += __shfl_xor_sync(0xffffffffu, p1, 1);
            p1 += __shfl_xor_sync(0xffffffffu, p1, 2);
            if (tg == 0) {
                atomicAdd(&g_tension[row0], p0);
                atomicAdd(&g_tension[row0 + 8], p1);
            }
        }
    }
}

// =============== merged dual-region bf16 split GEMM (R8/R10/R11/R13-validated) ===============
template <int MI, int NSPLIT, int MODE1, int MODE2>
__global__ void __launch_bounds__(256) gemm2(
    const bf16* __restrict__ Ahi, const bf16* __restrict__ Alo, int lda,
    const bf16* __restrict__ B1h, const bf16* __restrict__ B1l,
    const bf16* __restrict__ B2h, const bf16* __restrict__ B2l,
    bf16* __restrict__ Chi, bf16* __restrict__ Clo, int ldcb,
    float* __restrict__ C1, int ldc1,
    float* __restrict__ C2, int ldc2,
    int K,
    const float* __restrict__ bias1, const float* __restrict__ bias2)
{
    constexpr int TM = 64 * MI;
    constexpr int ABYTES = TM * 128;
    constexpr int BBYTES = 128 * 128;
    constexpr int STAGE = 2 * ABYTES + 2 * BBYTES;

    extern __shared__ __align__(1024) char smem[];
    const uint32_t sb = smem_u32(smem);
    const int tid = threadIdx.x;
    const int wid = tid >> 5, lane = tid & 31;
    const int wm = wid & 3, wn = wid >> 2;
    const int g = lane >> 2, tg = lane & 3;
    const int m0 = blockIdx.y * TM, n0 = blockIdx.x * 128;
    const int nc = K >> 6;

    const bool r1 = (n0 < NSPLIT);
    const int nb0 = r1 ? n0 : n0 - NSPLIT;
    const bf16* __restrict__ Bh = (r1 ? B1h : B2h) + (size_t)nb0 * K;
    const bf16* __restrict__ Bl = (r1 ? B1l : B2l) + (size_t)nb0 * K;
    const float* bias = r1 ? (bias1 ? bias1 + nb0 : nullptr)
                           : (bias2 ? bias2 + nb0 : nullptr);

    float acc[MI][8][4];
#pragma unroll
    for (int mi = 0; mi < MI; mi++)
#pragma unroll
        for (int ni = 0; ni < 8; ni++)
#pragma unroll
            for (int q = 0; q < 4; q++) acc[mi][ni][q] = 0.f;

    auto load_stage = [&](int c, int b) {
        const uint32_t s0 = sb + b * STAGE;
        const int k0 = c << 6;
#pragma unroll
        for (int it = 0; it < TM * 8 / 256; it++) {
            int idx = tid + it * 256;
            int row = idx >> 3, ch = idx & 7;
            uint32_t so = (uint32_t)(row << 7) + (uint32_t)((ch ^ (row & 7)) << 4);
            size_t go = (size_t)(m0 + row) * lda + k0 + ch * 8;
            cpa16(s0 + so, Ahi + go);
            cpa16(s0 + ABYTES + so, Alo + go);
        }
#pragma unroll
        for (int it = 0; it < 4; it++) {
            int idx = tid + it * 256;
            int row = idx >> 3, ch = idx & 7;
            uint32_t so = (uint32_t)(row << 7) + (uint32_t)((ch ^ (row & 7)) << 4);
            size_t go = (size_t)row * K + k0 + ch * 8;
            cpa16(s0 + 2 * ABYTES + so, Bh + go);
            cpa16(s0 + 2 * ABYTES + BBYTES + so, Bl + go);
        }
        cp_commit();
    };

    const int j = lane >> 3;
    const int arow_b = wm * (16 * MI) + (j & 1) * 8 + (lane & 7);
    const int brow_b = wn * 64 + (j >> 1) * 8 + (lane & 7);

    load_stage(0, 0);

    for (int c = 0; c < nc; c++) {
        cp_wait<0>();
        __syncthreads();

        const uint32_t sA = sb + (c & 1) * STAGE;
        const uint32_t sB = sA + 2 * ABYTES;

#pragma unroll
        for (int ks = 0; ks < 4; ks++) {
            uint32_t bh[8][2], bl[8][2];
            uint32_t ah[MI][4], al[MI][4];
            const int achunk = ks * 2 + (j >> 1);
            const int bchunk = ks * 2 + (j & 1);
#pragma unroll
            for (int nb = 0; nb < 4; nb++) {
                int r = brow_b + nb * 16;
                uint32_t off = (uint32_t)(r << 7) + (uint32_t)((bchunk ^ (r & 7)) << 4);
                uint32_t t0, t1, t2, t3;
                ldsm4(t0, t1, t2, t3, sB + off);
                bh[2 * nb][0] = t0; bh[2 * nb][1] = t1;
                bh[2 * nb + 1][0] = t2; bh[2 * nb + 1][1] = t3;
                ldsm4(t0, t1, t2, t3, sB + BBYTES + off);
                bl[2 * nb][0] = t0; bl[2 * nb][1] = t1;
                bl[2 * nb + 1][0] = t2; bl[2 * nb + 1][1] = t3;
            }
#pragma unroll
            for (int mi = 0; mi < MI; mi++) {
                int r = arow_b + mi * 16;
                uint32_t off = (uint32_t)(r << 7) + (uint32_t)((achunk ^ (r & 7)) << 4);
                ldsm4(ah[mi][0], ah[mi][1], ah[mi][2], ah[mi][3], sA + off);
                ldsm4(al[mi][0], al[mi][1], al[mi][2], al[mi][3], sA + ABYTES + off);
            }
#pragma unroll
            for (int mi = 0; mi < MI; mi++)
#pragma unroll
                for (int ni = 0; ni < 8; ni++)
                    mma16816(acc[mi][ni], ah[mi], bh[ni]);
#pragma unroll
            for (int mi = 0; mi < MI; mi++)
#pragma unroll
                for (int ni = 0; ni < 8; ni++)
                    mma16816(acc[mi][ni], ah[mi], bl[ni]);
#pragma unroll
            for (int mi = 0; mi < MI; mi++)
#pragma unroll
                for (int ni = 0; ni < 8; ni++)
                    mma16816(acc[mi][ni], al[mi], bh[ni]);
            if (ks == 0 && c + 1 < nc) load_stage(c + 1, (c + 1) & 1);
        }
    }

    if (r1) epilogue<MODE1, MI>(acc, m0, nb0, Chi, Clo, ldcb, C1, ldc1, bias, wm, wn, g, tg);
    else    epilogue<MODE2, MI>(acc, m0, nb0, Chi, Clo, ldcb, C2, ldc2, bias, wm, wn, g, tg);
}

// ---------------- prep (float4-vectorized critical path; side path as R13) ----------------
__global__ void k_prep_crit(const float* __restrict__ hiddens,
                            const float* __restrict__ W_hh,
                            const float* __restrict__ Wa1, const float* __restrict__ Wg1)
{
    const long S0 = 1048576L, S1 = 786432L, S2 = 65536L;   // float4 counts
    long i = (long)blockIdx.x * 256 + threadIdx.x;
    if (i < S0) {
        float4 v = ((const float4*)hiddens)[i];
        float2 a; a.x = v.x; a.y = v.y;
        float2 b; b.x = v.z; b.y = v.w;
        store_pair(g_hid_h, g_hid_l, (size_t)(4 * i), a);
        store_pair(g_hid_h, g_hid_l, (size_t)(4 * i) + 2, b);
    } else if (i < S0 + S1) {
        long k4 = i - S0;
        float4 v = ((const float4*)W_hh)[k4];
        float2 a; a.x = v.x; a.y = v.y;
        float2 b; b.x = v.z; b.y = v.w;
        store_pair(g_whh_h, g_whh_l, (size_t)(4 * k4), a);
        store_pair(g_whh_h, g_whh_l, (size_t)(4 * k4) + 2, b);
    } else if (i < S0 + S1 + S2) {
        long k = 4 * (i - S0 - S1);
        int r = (int)(k >> 10), c = (int)(k & 1023);
        const float* src = (r < 128) ? (Wa1 + (size_t)r * 2048 + 1024 + c)
                                     : (Wg1 + (size_t)(r - 128) * 2048 + 1024 + c);
        float4 v = *(const float4*)src;
        float2 a; a.x = v.x; a.y = v.y;
        float2 b; b.x = v.z; b.y = v.w;
        store_pair(g_b1_h, g_b1_l, (size_t)k, a);
        store_pair(g_b1_h, g_b1_l, (size_t)k + 2, b);
    }
}

__global__ void k_prep_side(const float* __restrict__ W_ih,
                            const float* __restrict__ Wa2, const float* __restrict__ Wg2)
{
    const long SW = 1572864L;
    long i = (long)blockIdx.x * 256 + threadIdx.x;
    if (i < SW) {
        long k = 2 * i;
        int r = (int)(k >> 10), c = (int)(k & 1023);
        const float* src = W_ih + (size_t)r * GIN + c;
        float2 v; v.x = src[0]; v.y = src[1];
        store_pair(g_wih_h, g_wih_l, (size_t)k, v);
    } else if (i < SW + 131072L) {
        long k = i - SW;
        int jr = (int)(k >> 7), m = (int)(k & 127);
        float va = Wa2[k], vg = -Wg2[k];
        bf16 h, l;
        split_bf16(va, h, l);
        g_wc2_h[jr * 256 + m] = h;          g_wc2_l[jr * 256 + m] = l;
        g_w2t_h[m * 1024 + jr] = h;         g_w2t_l[m * 1024 + jr] = l;
        split_bf16(vg, h, l);
        g_wc2_h[jr * 256 + 128 + m] = h;    g_wc2_l[jr * 256 + 128 + m] = l;
        g_w2t_h[(128 + m) * 1024 + jr] = h; g_w2t_l[(128 + m) * 1024 + jr] = l;
    }
}

__global__ void k_zero(const float* __restrict__ ba2, const float* __restrict__ bg2)
{
    int i = blockIdx.x * 256 + threadIdx.x;
    if (i < NT) g_counts[i] = 0.f;
    if (i < NF * NT) g_cft[i] = 0.f;
    if (i < NF * NT * HID) g_fsum_ft[i] = 0.f;
    if (i < 256) g_wa[i] = 0.f;
    if (i < N_CELLS) g_tension[i] = 0.f;
    if (i < 1024) g_bconst[i] = ba2[i] - bg2[i];
}

__global__ void k_bias1(const float* __restrict__ Wa1, const float* __restrict__ ba1,
                        const float* __restrict__ Wg1, const float* __restrict__ bg1,
                        const float* __restrict__ x)
{
    int b = blockIdx.x * 8 + (threadIdx.x >> 5);
    int lane = threadIdx.x & 31;
    const float* row = (b < 128) ? (Wa1 + (size_t)b * 2048) : (Wg1 + (size_t)(b - 128) * 2048);
    float s = 0.f;
    for (int jj = lane; jj < 1024; jj += 32) s += row[jj] * x[jj];
    s = wred(s);
    if (lane == 0)
        g_bias1[b] = s + ((b < 128) ? ba1[b] : bg1[b - 128]);
}

__global__ void k_vih(const float* __restrict__ W_ih, const float* __restrict__ b_ih)
{
    int k = blockIdx.x * 8 + (threadIdx.x >> 5);
    int lane = threadIdx.x & 31;
    const float* row = W_ih + (size_t)k * GIN;
    float s = 0.f;
    for (int jj = lane; jj < 1024; jj += 32) s += row[jj] * g_bconst[jj];
    s = wred(s);
    if (lane == 0) { g_vih[k] = s + b_ih[k]; g_wt[k] = row[1024]; }
}

__global__ void k_vote(const float* __restrict__ infl, const float* __restrict__ op,
                       const float* __restrict__ noise)
{
    int row = blockIdx.x;
    int tid = threadIdx.x;
    int lane = tid & 31, wid = tid >> 5;
    float acc[NT];
#pragma unroll
    for (int t = 0; t < NT; t++) acc[t] = 0.f;
    const float4* ir4 = (const float4*)(infl + (size_t)row * N_CELLS);
    for (int c4 = tid; c4 < N_CELLS / 4; c4 += 256) {
        float4 w4 = ir4[c4];
        float ws[4] = {w4.x, w4.y, w4.z, w4.w};
#pragma unroll
        for (int q = 0; q < 4; q++) {
            if (ws[q] != 0.f) {
                const float4* o4 = (const float4*)(op + (size_t)(4 * c4 + q) * NT);
                float4 a = o4[0], b = o4[1];
                acc[0] += ws[q] * a.x; acc[1] += ws[q] * a.y;
                acc[2] += ws[q] * a.z; acc[3] += ws[q] * a.w;
                acc[4] += ws[q] * b.x; acc[5] += ws[q] * b.y;
                acc[6] += ws[q] * b.z; acc[7] += ws[q] * b.w;
            }
        }
    }
    __shared__ float sh[8][NT];
#pragma unroll
    for (int t = 0; t < NT; t++) {
        float v = wred(acc[t]);
        if (lane == 0) sh[wid][t] = v;
    }
    __syncthreads();
    if (tid == 0) {
        float v[NT]; float sum = 0.f;
#pragma unroll
        for (int t = 0; t < NT; t++) {
            float s = 0.f;
#pragma unroll
            for (int w = 0; w < 8; w++) s += sh[w][t];
            float u = 0.7f * op[row * NT + t] + 0.3f * s + 0.01f * noise[row * NT + t];
            u = fmaxf(u, 0.01f);
            v[t] = u; sum += u;
        }
        float inv = 1.f / sum;
        int am = 0; float mx = v[0] * inv;
#pragma unroll
        for (int t = 1; t < NT; t++) {
            float u = v[t] * inv;
            if (u > mx) { mx = u; am = t; }
        }
        g_votes[row] = am;
        g_energy[row] = mx;
        atomicAdd(&g_counts[am], 1.f);
        atomicAdd(&g_cft[(row >> 9) * NT + am], 1.f);
    }
}

// float4-vectorized GRU with fused per-(faction,topic) segment sums
__global__ void k_gru(const float* __restrict__ hiddens)
{
    int i = blockIdx.x;
    float scale = 0.9f + 0.2f * g_energy[i];
    float t = g_tension[i] * (1.f / 1024.f);
    int vt = g_votes[i];
    int fa = i >> 9;
    const float4* gi = (const float4*)(g_gi + (size_t)i * G3);
    const float4* gh = (const float4*)(g_gh + (size_t)i * G3);
    const float4* wt = (const float4*)g_wt;
    const float4* hd = (const float4*)(hiddens + (size_t)i * 1024);
    float4* nh = (float4*)(g_nh + (size_t)i * HID);
    int j4 = threadIdx.x;
    float4 gir = gi[j4],        ghr = gh[j4];
    float4 giz = gi[j4 + 256],  ghz = gh[j4 + 256];
    float4 gin = gi[j4 + 512],  ghn = gh[j4 + 512];
    float4 wtr = wt[j4], wtz = wt[j4 + 256], wtn = wt[j4 + 512];
    float4 h = hd[j4];
    float4 o;
    {
        float r = 1.f / (1.f + expf(-(gir.x + t * wtr.x + ghr.x)));
        float z = 1.f / (1.f + expf(-(giz.x + t * wtz.x + ghz.x)));
        float n = tanhf(gin.x + t * wtn.x + r * ghn.x);
        o.x = fminf(fmaxf(((1.f - z) * n + z * h.x) * scale, -10.f), 10.f);
    }
    {
        float r = 1.f / (1.f + expf(-(gir.y + t * wtr.y + ghr.y)));
        float z = 1.f / (1.f + expf(-(giz.y + t * wtz.y + ghz.y)));
        float n = tanhf(gin.y + t * wtn.y + r * ghn.y);
        o.y = fminf(fmaxf(((1.f - z) * n + z * h.y) * scale, -10.f), 10.f);
    }
    {
        float r = 1.f / (1.f + expf(-(gir.z + t * wtr.z + ghr.z)));
        float z = 1.f / (1.f + expf(-(giz.z + t * wtz.z + ghz.z)));
        float n = tanhf(gin.z + t * wtn.z + r * ghn.z);
        o.z = fminf(fmaxf(((1.f - z) * n + z * h.z) * scale, -10.f), 10.f);
    }
    {
        float r = 1.f / (1.f + expf(-(gir.w + t * wtr.w + ghr.w)));
        float z = 1.f / (1.f + expf(-(giz.w + t * wtz.w + ghz.w)));
        float n = tanhf(gin.w + t * wtn.w + r * ghn.w);
        o.w = fminf(fmaxf(((1.f - z) * n + z * h.w) * scale, -10.f), 10.f);
    }
    nh[j4] = o;
    float* sums = g_fsum_ft + ((size_t)(fa * NT + vt)) * HID + 4 * j4;
    atomicAdd(sums + 0, o.x);
    atomicAdd(sums + 1, o.y);
    atomicAdd(sums + 2, o.z);
    atomicAdd(sums + 3, o.w);
}

__global__ void k_fblend()
{
    int c = blockIdx.x * 256 + threadIdx.x;
    float sums_t[NT];
#pragma unroll
    for (int t = 0; t < NT; t++) {
        float s = 0.f;
#pragma unroll
        for (int f = 0; f < NF; f++)
            s += g_fsum_ft[(size_t)(f * NT + t) * HID + c];
        sums_t[t] = s;
        g_sums[t * HID + c] = s;
    }
    float glob = 0.f;
#pragma unroll
    for (int f = 0; f < NF; f++) {
        float v = 0.f;
#pragma unroll
        for (int t = 0; t < NT; t++) {
            float raw = g_fsum_ft[(size_t)(f * NT + t) * HID + c];
            float cnt = g_counts[t];
            if (cnt >= 2.f)
                v += 0.85f * raw + 0.15f * g_cft[f * NT + t] * (sums_t[t] / fmaxf(cnt, 1.f));
            else
                v += raw;
        }
        g_fsums[f * HID + c] = v;
        glob += v;
    }
    g_glob[c] = glob * (1.f / 4096.f);
}

__global__ void k_final(float* __restrict__ out_nh, const int* __restrict__ step)
{
    int i = blockIdx.x;
    int f = i >> 9;
    int t = g_votes[i];
    float cnt = g_counts[t];
    bool ap = (cnt >= 2.f);
    float invc = 1.f / fmaxf(cnt, 1.f);
    bool dcz = (*step > 5) && ((i & 511) < 128);
    for (int jj = threadIdx.x; jj < HID; jj += 256) {
        float v = g_nh[(size_t)i * HID + jj];
        if (ap) v = 0.85f * v + 0.15f * g_sums[t * HID + jj] * invc;
        float fm = g_fsums[f * HID + jj] * (1.f / 512.f);
        v = 0.85f * v + 0.15f * fm;
        if (dcz) v = 0.85f * v + 0.15f * g_glob[jj];
        out_nh[(size_t)i * HID + jj] = v;
    }
}

__global__ void k_softmax(float* __restrict__ out_avg)
{
    __shared__ float sh[1024];
    int tid = threadIdx.x;
    float t4[4];
    float mx = -1e30f, av = 0.f;
#pragma unroll
    for (int q = 0; q < 4; q++) {
        t4[q] = g_tension[tid + q * 1024] * (1.f / 1024.f);
        mx = fmaxf(mx, t4[q]);
        av += t4[q];
    }
    sh[tid] = mx; __syncthreads();
    for (int o = 512; o > 0; o >>= 1) {
        if (tid < o) sh[tid] = fmaxf(sh[tid], sh[tid + o]);
        __syncthreads();
    }
    float M = sh[0]; __syncthreads();
    float sm = 0.f;
#pragma unroll
    for (int q = 0; q < 4; q++) {
        float e = expf(t4[q] - M);
        g_w[tid + q * 1024] = e;
        sm += e;
    }
    sh[tid] = sm; __syncthreads();
    for (int o = 512; o > 0; o >>= 1) {
        if (tid < o) sh[tid] += sh[tid + o];
        __syncthreads();
    }
    float inv = 1.f / sh[0]; __syncthreads();
#pragma unroll
    for (int q = 0; q < 4; q++) g_w[tid + q * 1024] *= inv;
    sh[tid] = av; __syncthreads();
    for (int o = 512; o > 0; o >>= 1) {
        if (tid < o) sh[tid] += sh[tid + o];
        __syncthreads();
    }
    if (tid == 0) out_avg[0] = sh[0] * (1.f / 4096.f);
}

__global__ void k_wA()
{
    int c = threadIdx.x;
    int r0 = blockIdx.x * 128;
    float acc = 0.f;
    for (int r = r0; r < r0 + 128; r++) {
        float w = g_w[r];
        float v = __bfloat162float(g_a1g1_h[(size_t)r * 256 + c])
                + __bfloat162float(g_a1g1_l[(size_t)r * 256 + c]);
        acc += w * v;
    }
    atomicAdd(&g_wa[c], acc);
}

__global__ void k_comb2()
{
    int jr = blockIdx.x * 8 + (threadIdx.x >> 5);
    int lane = threadIdx.x & 31;
    float s = 0.f;
    for (int m = lane; m < 256; m += 32) {
        float wv = __bfloat162float(g_wc2_h[(size_t)jr * 256 + m])
                 + __bfloat162float(g_wc2_l[(size_t)jr * 256 + m]);
        s += g_wa[m] * wv;
    }
    s = wred(s);
    if (lane == 0) g_combined[jr] = s + g_bconst[jr];
}

__global__ void k_pred(const float* __restrict__ Wo, const float* __restrict__ bo,
                       float* __restrict__ out_pred)
{
    int i = blockIdx.x * 8 + (threadIdx.x >> 5);
    int lane = threadIdx.x & 31;
    const float* row = Wo + (size_t)i * 1024;
    float s = 0.f;
    for (int jj = lane; jj < 1024; jj += 32) s += g_combined[jj] * row[jj];
    s = wred(s);
    if (lane == 0) out_pred[i] = s + bo[i];
}

// ---------------- launch ----------------
template <typename T>
static T* symp(const void* s)
{
    void* p = nullptr;
    cudaGetSymbolAddress(&p, s);
    return (T*)p;
}

#define SMEM_MI1 (2 * (2 * 64 * 128 + 2 * 128 * 128))    // 96 KB
#define SMEM_MI4 (2 * (2 * 256 * 128 + 2 * 128 * 128))   // 192 KB

extern "C" void kernel_launch(void* const* d_in, const int* in_sizes, int n_in,
                              void* d_out, int out_size)
{
    const float* x        = (const float*)d_in[0];
    const float* hiddens  = (const float*)d_in[1];
    const float* opinions = (const float*)d_in[2];
    const float* influence= (const float*)d_in[3];
    const float* noise    = (const float*)d_in[4];
    const float* Wa1 = (const float*)d_in[5];
    const float* ba1 = (const float*)d_in[6];
    const float* Wa2 = (const float*)d_in[7];
    const float* ba2 = (const float*)d_in[8];
    const float* Wg1 = (const float*)d_in[9];
    const float* bg1 = (const float*)d_in[10];
    const float* Wg2 = (const float*)d_in[11];
    const float* bg2 = (const float*)d_in[12];
    const float* W_ih = (const float*)d_in[13];
    const float* b_ih = (const float*)d_in[14];
    const float* W_hh = (const float*)d_in[15];
    const float* b_hh = (const float*)d_in[16];
    const float* Wo  = (const float*)d_in[17];
    const float* bo  = (const float*)d_in[18];
    const int*   step = (const int*)d_in[19];

    float* out = (float*)d_out;
    float* out_pred = out;
    float* out_avg  = out + 1024;
    float* out_nh   = out + 1025;

    bf16* pHidH = symp<bf16>(g_hid_h);  bf16* pHidL = symp<bf16>(g_hid_l);
    bf16* pWihH = symp<bf16>(g_wih_h);  bf16* pWihL = symp<bf16>(g_wih_l);
    bf16* pWhhH = symp<bf16>(g_whh_h);  bf16* pWhhL = symp<bf16>(g_whh_l);
    bf16* pB1H  = symp<bf16>(g_b1_h);   bf16* pB1L  = symp<bf16>(g_b1_l);
    bf16* pWc2H = symp<bf16>(g_wc2_h);  bf16* pWc2L = symp<bf16>(g_wc2_l);
    bf16* pW2TH = symp<bf16>(g_w2t_h);  bf16* pW2TL = symp<bf16>(g_w2t_l);
    bf16* pMcH  = symp<bf16>(g_mcat_h); bf16* pMcL  = symp<bf16>(g_mcat_l);
    bf16* pAgH  = symp<bf16>(g_a1g1_h); bf16* pAgL  = symp<bf16>(g_a1g1_l);
    float* pGi  = symp<float>(g_gi);
    float* pGh  = symp<float>(g_gh);
    float* pBias1 = symp<float>(g_bias1);
    float* pBconst= symp<float>(g_bconst);
    float* pVih = symp<float>(g_vih);

    static bool init_done = false;
    static bool use_streams = false;
    static cudaStream_t sM = nullptr, sV = nullptr, sG = nullptr;
    static cudaEvent_t ev0 = nullptr, evPC = nullptr, evM = nullptr, evBV = nullptr,
                       evV = nullptr, evG = nullptr, evT = nullptr, evP = nullptr;
    if (!init_done) {
        init_done = true;
        cudaFuncSetAttribute(gemm2<1, 4096, 3, 0>,   // Mcat
                             cudaFuncAttributeMaxDynamicSharedMemorySize, SMEM_MI1);
        cudaFuncSetAttribute(gemm2<1, 4096, 1, 0>,   // A1G1
                             cudaFuncAttributeMaxDynamicSharedMemorySize, SMEM_MI1);
        cudaFuncSetAttribute(gemm2<4, 4096, 0, 0>,   // gh
                             cudaFuncAttributeMaxDynamicSharedMemorySize, SMEM_MI4);
        cudaFuncSetAttribute(gemm2<4, 3072, 0, 2>,   // gi | tension
                             cudaFuncAttributeMaxDynamicSharedMemorySize, SMEM_MI4);
        use_streams =
            (cudaStreamCreateWithFlags(&sM, cudaStreamNonBlocking) == cudaSuccess) &&
            (cudaStreamCreateWithFlags(&sV, cudaStreamNonBlocking) == cudaSuccess) &&
            (cudaStreamCreateWithFlags(&sG, cudaStreamNonBlocking) == cudaSuccess) &&
            (cudaEventCreateWithFlags(&ev0, cudaEventDisableTiming) == cudaSuccess) &&
            (cudaEventCreateWithFlags(&evPC, cudaEventDisableTiming) == cudaSuccess) &&
            (cudaEventCreateWithFlags(&evM, cudaEventDisableTiming) == cudaSuccess) &&
            (cudaEventCreateWithFlags(&evBV, cudaEventDisableTiming) == cudaSuccess) &&
            (cudaEventCreateWithFlags(&evV, cudaEventDisableTiming) == cudaSuccess) &&
            (cudaEventCreateWithFlags(&evG, cudaEventDisableTiming) == cudaSuccess) &&
            (cudaEventCreateWithFlags(&evT, cudaEventDisableTiming) == cudaSuccess) &&
            (cudaEventCreateWithFlags(&evP, cudaEventDisableTiming) == cudaSuccess);
    }

    cudaStream_t m = use_streams ? sM : (cudaStream_t)0;
    cudaStream_t vv = use_streams ? sV : (cudaStream_t)0;
    cudaStream_t gg = use_streams ? sG : (cudaStream_t)0;

    k_zero<<<256, 256>>>(ba2, bg2);

    if (use_streams) {
        cudaEventRecord(ev0, 0);
        cudaStreamWaitEvent(vv, ev0, 0);
        cudaStreamWaitEvent(m, ev0, 0);
    }
    k_vote<<<N_CELLS, 256, 0, vv>>>(influence, opinions, noise);
    if (use_streams) cudaEventRecord(evV, vv);

    // side stream: bias1, vih, prep_side, Mcat
    k_bias1<<<32, 256, 0, m>>>(Wa1, ba1, Wg1, bg1, x);
    k_vih<<<G3 / 8, 256, 0, m>>>(W_ih, b_ih);
    if (use_streams) cudaEventRecord(evBV, m);
    k_prep_side<<<6656, 256, 0, m>>>(W_ih, Wa2, Wg2);
    gemm2<1, 4096, 3, 0><<<dim3(2, 48), 256, SMEM_MI1, m>>>(
        pWihH, pWihL, 1024,
        pW2TH, pW2TL, nullptr, nullptr,
        pMcH, pMcL, 256,
        nullptr, 0, nullptr, 0,
        1024, nullptr, nullptr);
    if (use_streams) cudaEventRecord(evM, m);

    // critical prep on stream 0 (float4)
    k_prep_crit<<<7424, 256>>>(hiddens, W_hh, Wa1, Wg1);
    if (use_streams) cudaEventRecord(evPC, 0);

    // gh GEMM on its own stream
    if (use_streams) cudaStreamWaitEvent(gg, evPC, 0);
    gemm2<4, 4096, 0, 0><<<dim3(24, 16), 256, SMEM_MI4, gg>>>(
        pHidH, pHidL, 1024,
        pWhhH, pWhhL, nullptr, nullptr,
        nullptr, nullptr, 0,
        pGh, G3, nullptr, 0,
        1024, b_hh, nullptr);
    if (use_streams) cudaEventRecord(evG, gg);

    // A1G1 GEMM on stream 0
    if (use_streams) cudaStreamWaitEvent(0, evBV, 0);
    gemm2<1, 4096, 1, 0><<<dim3(2, 64), 256, SMEM_MI1>>>(
        pHidH, pHidL, 1024,
        pB1H, pB1L, nullptr, nullptr,
        pAgH, pAgL, 256,
        nullptr, 0, nullptr, 0,
        1024, pBias1, nullptr);

    // gi | tension GEMM on stream 0
    if (use_streams) cudaStreamWaitEvent(0, evM, 0);
    gemm2<4, 3072, 0, 2><<<dim3(32, 16), 256, SMEM_MI4>>>(
        pAgH, pAgL, 256,
        pMcH, pMcL, pWc2H, pWc2L,
        nullptr, nullptr, 0,
        pGi, G3, nullptr, 0,
        256, pVih, pBconst);
    if (use_streams) { cudaEventRecord(evT, 0); cudaStreamWaitEvent(m, evT, 0); }

    // softmax -> pred chain on side stream
    k_softmax<<<1, 1024, 0, m>>>(out_avg);
    k_wA<<<32, 256, 0, m>>>();
    k_comb2<<<128, 256, 0, m>>>();
    k_pred<<<128, 256, 0, m>>>(Wo, bo, out_pred);
    if (use_streams) cudaEventRecord(evP, m);

    // GRU chain
    if (use_streams) { cudaStreamWaitEvent(0, evG, 0); cudaStreamWaitEvent(0, evV, 0); }
    k_gru<<<N_CELLS, 256>>>(hiddens);
    k_fblend<<<4, 256>>>();
    k_final<<<N_CELLS, 256>>>(out_nh, step);

    if (use_streams) cudaStreamWaitEvent(0, evP, 0);
}

// round 16
// speedup vs baseline: 1.3185x; 1.1845x over previous
#include <cuda_runtime.h>
#include <cuda_fp16.h>
#include <math.h>
#include <stdint.h>

#define N_CELLS 4096
#define IN_DIM 1024
#define HID 1024
#define OUT_DIM 1024
#define NT 8
#define NF 8
#define GIN 1025
#define G3 3072

typedef __half hf;

// ---------------- scratch (device globals) ----------------
__device__ hf g_hid_h[N_CELLS * HID],   g_hid_l[N_CELLS * HID];
__device__ hf g_wih_h[G3 * 1024],       g_wih_l[G3 * 1024];
__device__ hf g_whh_h[G3 * 1024],       g_whh_l[G3 * 1024];
__device__ hf g_b1_h[256 * 1024],       g_b1_l[256 * 1024];
__device__ hf g_wc2_h[1024 * 256],      g_wc2_l[1024 * 256];
__device__ hf g_w2t_h[256 * 1024],      g_w2t_l[256 * 1024];
__device__ hf g_mcat_h[G3 * 256],       g_mcat_l[G3 * 256];
__device__ hf g_a1g1_h[N_CELLS * 256],  g_a1g1_l[N_CELLS * 256];
__device__ float g_gi[N_CELLS * G3];
__device__ float g_gh[N_CELLS * G3];
__device__ float g_nh[N_CELLS * HID];
__device__ float g_tension[N_CELLS];
__device__ float g_energy[N_CELLS];
__device__ int   g_votes[N_CELLS];
__device__ float g_bias1[256];
__device__ float g_bconst[1024];
__device__ float g_vih[G3];
__device__ float g_wt[G3];
__device__ float g_counts[NT];
__device__ float g_cft[NF * NT];
__device__ float g_fsum_ft[NF * NT * HID];
__device__ float g_sums[NT * HID];
__device__ float g_fsums[NF * HID];
__device__ float g_glob[HID];
__device__ float g_w[N_CELLS];
__device__ float g_wa[256];
__device__ float g_combined[OUT_DIM];

// ---------------- asm helpers ----------------
__device__ __forceinline__ uint32_t smem_u32(const void* p) {
    uint32_t a;
    asm("{ .reg .u64 t; cvta.to.shared.u64 t, %1; cvt.u32.u64 %0, t; }" : "=r"(a) : "l"(p));
    return a;
}
__device__ __forceinline__ void cpa16(uint32_t s, const void* g) {
    asm volatile("cp.async.cg.shared.global [%0], [%1], 16;" :: "r"(s), "l"(g));
}
__device__ __forceinline__ void cp_commit() {
    asm volatile("cp.async.commit_group;" ::: "memory");
}
template <int N>
__device__ __forceinline__ void cp_wait() {
    asm volatile("cp.async.wait_group %0;" :: "n"(N) : "memory");
}
__device__ __forceinline__ void ldsm4(uint32_t& r0, uint32_t& r1, uint32_t& r2, uint32_t& r3,
                                      uint32_t a) {
    asm volatile("ldmatrix.sync.aligned.m8n8.x4.shared.b16 {%0,%1,%2,%3}, [%4];"
                 : "=r"(r0), "=r"(r1), "=r"(r2), "=r"(r3) : "r"(a));
}
__device__ __forceinline__ void mma16816(float c[4], const uint32_t a[4], const uint32_t b[2])
{
    asm("mma.sync.aligned.m16n8k16.row.col.f32.f16.f16.f32 "
        "{%0,%1,%2,%3}, {%4,%5,%6,%7}, {%8,%9}, {%0,%1,%2,%3};"
        : "+f"(c[0]), "+f"(c[1]), "+f"(c[2]), "+f"(c[3])
        : "r"(a[0]), "r"(a[1]), "r"(a[2]), "r"(a[3]), "r"(b[0]), "r"(b[1]));
}
__device__ __forceinline__ void split_f16(float x, hf& hi, hf& lo)
{
    hi = __float2half_rn(x);
    lo = __float2half_rn(x - __half2float(hi));
}
__device__ __forceinline__ void store_pair(hf* H, hf* L, size_t idx, float2 v)
{
    hf hx, lx, hy, ly;
    split_f16(v.x, hx, lx);
    split_f16(v.y, hy, ly);
    *(__half2*)(H + idx) = __halves2half2(hx, hy);
    *(__half2*)(L + idx) = __halves2half2(lx, ly);
}
__device__ __forceinline__ float wred(float v)
{
    v += __shfl_xor_sync(0xffffffffu, v, 16);
    v += __shfl_xor_sync(0xffffffffu, v, 8);
    v += __shfl_xor_sync(0xffffffffu, v, 4);
    v += __shfl_xor_sync(0xffffffffu, v, 2);
    v += __shfl_xor_sync(0xffffffffu, v, 1);
    return v;
}

// ---- epilogue modes: 0 = fp32 write, 1 = f16 split + relu, 2 = sumsq-only, 3 = f16 split ----
template <int MODE, int MI>
__device__ __forceinline__ void epilogue(
    float (*acc)[8][4], int m0, int nb0,
    hf* __restrict__ Chi, hf* __restrict__ Clo, int ldcb,
    float* __restrict__ Cf, int ldcf,
    const float* __restrict__ bias,
    int wm, int wn, int g, int tg)
{
#pragma unroll
    for (int mi = 0; mi < MI; mi++) {
        int row0 = m0 + wm * (16 * MI) + mi * 16 + g;
        float p0 = 0.f, p1 = 0.f;
#pragma unroll
        for (int ni = 0; ni < 8; ni++) {
            int lc = wn * 64 + ni * 8 + tg * 2;
            float b0 = bias ? bias[lc] : 0.f;
            float b1 = bias ? bias[lc + 1] : 0.f;
            float v0 = acc[mi][ni][0] + b0;
            float v1 = acc[mi][ni][1] + b1;
            float v2 = acc[mi][ni][2] + b0;
            float v3 = acc[mi][ni][3] + b1;
            if (MODE == 1) {
                v0 = fmaxf(v0, 0.f); v1 = fmaxf(v1, 0.f);
                v2 = fmaxf(v2, 0.f); v3 = fmaxf(v3, 0.f);
            }
            if (MODE == 2) { p0 += v0 * v0 + v1 * v1; p1 += v2 * v2 + v3 * v3; }
            if (MODE == 1 || MODE == 3) {
                float2 a; a.x = v0; a.y = v1;
                float2 b; b.x = v2; b.y = v3;
                store_pair(Chi, Clo, (size_t)row0 * ldcb + nb0 + lc, a);
                store_pair(Chi, Clo, (size_t)(row0 + 8) * ldcb + nb0 + lc, b);
            }
            if (MODE == 0) {
                float2 q0; q0.x = v0; q0.y = v1;
                float2 q1; q1.x = v2; q1.y = v3;
                *(float2*)(Cf + (size_t)row0 * ldcf + nb0 + lc) = q0;
                *(float2*)(Cf + (size_t)(row0 + 8) * ldcf + nb0 + lc) = q1;
            }
        }
        if (MODE == 2) {
            p0 += __shfl_xor_sync(0xffffffffu, p0, 1);
            p0 += __shfl_xor_sync(0xffffffffu, p0, 2);
            p1 += __shfl_xor_sync(0xffffffffu, p1, 1);
            p1 += __shfl_xor_sync(0xffffffffu, p1, 2);
            if (tg == 0) {
                atomicAdd(&g_tension[row0], p0);
                atomicAdd(&g_tension[row0 + 8], p1);
            }
        }
    }
}

// =============== merged dual-region fp16 split GEMM ===============
// NPROD=3: hh + h*bl + al*bh (full). NPROD=2: hh + al*bh (B-lo never loaded).
template <int MI, int NSPLIT, int MODE1, int MODE2, int NPROD>
__global__ void __launch_bounds__(256) gemm2(
    const hf* __restrict__ Ahi, const hf* __restrict__ Alo, int lda,
    const hf* __restrict__ B1h, const hf* __restrict__ B1l,
    const hf* __restrict__ B2h, const hf* __restrict__ B2l,
    hf* __restrict__ Chi, hf* __restrict__ Clo, int ldcb,
    float* __restrict__ C1, int ldc1,
    float* __restrict__ C2, int ldc2,
    int K,
    const float* __restrict__ bias1, const float* __restrict__ bias2)
{
    constexpr int TM = 64 * MI;
    constexpr int ABYTES = TM * 128;
    constexpr int BBYTES = 128 * 128;
    constexpr int STAGE = 2 * ABYTES + 2 * BBYTES;

    extern __shared__ __align__(1024) char smem[];
    const uint32_t sb = smem_u32(smem);
    const int tid = threadIdx.x;
    const int wid = tid >> 5, lane = tid & 31;
    const int wm = wid & 3, wn = wid >> 2;
    const int g = lane >> 2, tg = lane & 3;
    const int m0 = blockIdx.y * TM, n0 = blockIdx.x * 128;
    const int nc = K >> 6;

    const bool r1 = (n0 < NSPLIT);
    const int nb0 = r1 ? n0 : n0 - NSPLIT;
    const hf* __restrict__ Bh = (r1 ? B1h : B2h) + (size_t)nb0 * K;
    const hf* __restrict__ Bl = (NPROD == 3) ? ((r1 ? B1l : B2l) + (size_t)nb0 * K) : nullptr;
    const float* bias = r1 ? (bias1 ? bias1 + nb0 : nullptr)
                           : (bias2 ? bias2 + nb0 : nullptr);

    float acc[MI][8][4];
#pragma unroll
    for (int mi = 0; mi < MI; mi++)
#pragma unroll
        for (int ni = 0; ni < 8; ni++)
#pragma unroll
            for (int q = 0; q < 4; q++) acc[mi][ni][q] = 0.f;

    auto load_stage = [&](int c, int b) {
        const uint32_t s0 = sb + b * STAGE;
        const int k0 = c << 6;
#pragma unroll
        for (int it = 0; it < TM * 8 / 256; it++) {
            int idx = tid + it * 256;
            int row = idx >> 3, ch = idx & 7;
            uint32_t so = (uint32_t)(row << 7) + (uint32_t)((ch ^ (row & 7)) << 4);
            size_t go = (size_t)(m0 + row) * lda + k0 + ch * 8;
            cpa16(s0 + so, Ahi + go);
            cpa16(s0 + ABYTES + so, Alo + go);
        }
#pragma unroll
        for (int it = 0; it < 4; it++) {
            int idx = tid + it * 256;
            int row = idx >> 3, ch = idx & 7;
            uint32_t so = (uint32_t)(row << 7) + (uint32_t)((ch ^ (row & 7)) << 4);
            size_t go = (size_t)row * K + k0 + ch * 8;
            cpa16(s0 + 2 * ABYTES + so, Bh + go);
            if (NPROD == 3)
                cpa16(s0 + 2 * ABYTES + BBYTES + so, Bl + go);
        }
        cp_commit();
    };

    const int j = lane >> 3;
    const int arow_b = wm * (16 * MI) + (j & 1) * 8 + (lane & 7);
    const int brow_b = wn * 64 + (j >> 1) * 8 + (lane & 7);

    load_stage(0, 0);

    for (int c = 0; c < nc; c++) {
        cp_wait<0>();
        __syncthreads();

        const uint32_t sA = sb + (c & 1) * STAGE;
        const uint32_t sB = sA + 2 * ABYTES;

#pragma unroll
        for (int ks = 0; ks < 4; ks++) {
            uint32_t bh[8][2], bl[8][2];
            uint32_t ah[MI][4], al[MI][4];
            const int achunk = ks * 2 + (j >> 1);
            const int bchunk = ks * 2 + (j & 1);
#pragma unroll
            for (int nb = 0; nb < 4; nb++) {
                int r = brow_b + nb * 16;
                uint32_t off = (uint32_t)(r << 7) + (uint32_t)((bchunk ^ (r & 7)) << 4);
                uint32_t t0, t1, t2, t3;
                ldsm4(t0, t1, t2, t3, sB + off);
                bh[2 * nb][0] = t0; bh[2 * nb][1] = t1;
                bh[2 * nb + 1][0] = t2; bh[2 * nb + 1][1] = t3;
                if (NPROD == 3) {
                    ldsm4(t0, t1, t2, t3, sB + BBYTES + off);
                    bl[2 * nb][0] = t0; bl[2 * nb][1] = t1;
                    bl[2 * nb + 1][0] = t2; bl[2 * nb + 1][1] = t3;
                }
            }
#pragma unroll
            for (int mi = 0; mi < MI; mi++) {
                int r = arow_b + mi * 16;
                uint32_t off = (uint32_t)(r << 7) + (uint32_t)((achunk ^ (r & 7)) << 4);
                ldsm4(ah[mi][0], ah[mi][1], ah[mi][2], ah[mi][3], sA + off);
                ldsm4(al[mi][0], al[mi][1], al[mi][2], al[mi][3], sA + ABYTES + off);
            }
#pragma unroll
            for (int mi = 0; mi < MI; mi++)
#pragma unroll
                for (int ni = 0; ni < 8; ni++)
                    mma16816(acc[mi][ni], ah[mi], bh[ni]);
            if (NPROD == 3) {
#pragma unroll
                for (int mi = 0; mi < MI; mi++)
#pragma unroll
                    for (int ni = 0; ni < 8; ni++)
                        mma16816(acc[mi][ni], ah[mi], bl[ni]);
            }
#pragma unroll
            for (int mi = 0; mi < MI; mi++)
#pragma unroll
                for (int ni = 0; ni < 8; ni++)
                    mma16816(acc[mi][ni], al[mi], bh[ni]);
            if (ks == 0 && c + 1 < nc) load_stage(c + 1, (c + 1) & 1);
        }
    }

    if (r1) epilogue<MODE1, MI>(acc, m0, nb0, Chi, Clo, ldcb, C1, ldc1, bias, wm, wn, g, tg);
    else    epilogue<MODE2, MI>(acc, m0, nb0, Chi, Clo, ldcb, C2, ldc2, bias, wm, wn, g, tg);
}

// ---------------- prep ----------------
__global__ void k_prep_crit(const float* __restrict__ hiddens,
                            const float* __restrict__ W_hh,
                            const float* __restrict__ Wa1, const float* __restrict__ Wg1)
{
    const long S0 = 1048576L, S1 = 786432L, S2 = 65536L;   // float4 counts
    long i = (long)blockIdx.x * 256 + threadIdx.x;
    if (i < S0) {
        float4 v = ((const float4*)hiddens)[i];
        float2 a; a.x = v.x; a.y = v.y;
        float2 b; b.x = v.z; b.y = v.w;
        store_pair(g_hid_h, g_hid_l, (size_t)(4 * i), a);
        store_pair(g_hid_h, g_hid_l, (size_t)(4 * i) + 2, b);
    } else if (i < S0 + S1) {
        long k4 = i - S0;
        float4 v = ((const float4*)W_hh)[k4];
        float2 a; a.x = v.x; a.y = v.y;
        float2 b; b.x = v.z; b.y = v.w;
        store_pair(g_whh_h, g_whh_l, (size_t)(4 * k4), a);
        store_pair(g_whh_h, g_whh_l, (size_t)(4 * k4) + 2, b);
    } else if (i < S0 + S1 + S2) {
        long k = 4 * (i - S0 - S1);
        int r = (int)(k >> 10), c = (int)(k & 1023);
        const float* src = (r < 128) ? (Wa1 + (size_t)r * 2048 + 1024 + c)
                                     : (Wg1 + (size_t)(r - 128) * 2048 + 1024 + c);
        float4 v = *(const float4*)src;
        float2 a; a.x = v.x; a.y = v.y;
        float2 b; b.x = v.z; b.y = v.w;
        store_pair(g_b1_h, g_b1_l, (size_t)k, a);
        store_pair(g_b1_h, g_b1_l, (size_t)k + 2, b);
    }
}

__global__ void k_prep_side(const float* __restrict__ W_ih,
                            const float* __restrict__ Wa2, const float* __restrict__ Wg2)
{
    const long SW = 1572864L;
    long i = (long)blockIdx.x * 256 + threadIdx.x;
    if (i < SW) {
        long k = 2 * i;
        int r = (int)(k >> 10), c = (int)(k & 1023);
        const float* src = W_ih + (size_t)r * GIN + c;
        float2 v; v.x = src[0]; v.y = src[1];
        store_pair(g_wih_h, g_wih_l, (size_t)k, v);
    } else if (i < SW + 131072L) {
        long k = i - SW;
        int jr = (int)(k >> 7), m = (int)(k & 127);
        float va = Wa2[k], vg = -Wg2[k];
        hf h, l;
        split_f16(va, h, l);
        g_wc2_h[jr * 256 + m] = h;          g_wc2_l[jr * 256 + m] = l;
        g_w2t_h[m * 1024 + jr] = h;         g_w2t_l[m * 1024 + jr] = l;
        split_f16(vg, h, l);
        g_wc2_h[jr * 256 + 128 + m] = h;    g_wc2_l[jr * 256 + 128 + m] = l;
        g_w2t_h[(128 + m) * 1024 + jr] = h; g_w2t_l[(128 + m) * 1024 + jr] = l;
    }
}

__global__ void k_zero(const float* __restrict__ ba2, const float* __restrict__ bg2)
{
    int i = blockIdx.x * 256 + threadIdx.x;
    if (i < NT) g_counts[i] = 0.f;
    if (i < NF * NT) g_cft[i] = 0.f;
    if (i < NF * NT * HID) g_fsum_ft[i] = 0.f;
    if (i < 256) g_wa[i] = 0.f;
    if (i < N_CELLS) g_tension[i] = 0.f;
    if (i < 1024) g_bconst[i] = ba2[i] - bg2[i];
}

__global__ void k_bias1(const float* __restrict__ Wa1, const float* __restrict__ ba1,
                        const float* __restrict__ Wg1, const float* __restrict__ bg1,
                        const float* __restrict__ x)
{
    int b = blockIdx.x * 8 + (threadIdx.x >> 5);
    int lane = threadIdx.x & 31;
    const float* row = (b < 128) ? (Wa1 + (size_t)b * 2048) : (Wg1 + (size_t)(b - 128) * 2048);
    float s = 0.f;
    for (int jj = lane; jj < 1024; jj += 32) s += row[jj] * x[jj];
    s = wred(s);
    if (lane == 0)
        g_bias1[b] = s + ((b < 128) ? ba1[b] : bg1[b - 128]);
}

__global__ void k_vih(const float* __restrict__ W_ih, const float* __restrict__ b_ih)
{
    int k = blockIdx.x * 8 + (threadIdx.x >> 5);
    int lane = threadIdx.x & 31;
    const float* row = W_ih + (size_t)k * GIN;
    float s = 0.f;
    for (int jj = lane; jj < 1024; jj += 32) s += row[jj] * g_bconst[jj];
    s = wred(s);
    if (lane == 0) { g_vih[k] = s + b_ih[k]; g_wt[k] = row[1024]; }
}

__global__ void k_vote(const float* __restrict__ infl, const float* __restrict__ op,
                       const float* __restrict__ noise)
{
    int row = blockIdx.x;
    int tid = threadIdx.x;
    int lane = tid & 31, wid = tid >> 5;
    float acc[NT];
#pragma unroll
    for (int t = 0; t < NT; t++) acc[t] = 0.f;
    const float4* ir4 = (const float4*)(infl + (size_t)row * N_CELLS);
    for (int c4 = tid; c4 < N_CELLS / 4; c4 += 256) {
        float4 w4 = ir4[c4];
        float ws[4] = {w4.x, w4.y, w4.z, w4.w};
#pragma unroll
        for (int q = 0; q < 4; q++) {
            if (ws[q] != 0.f) {
                const float4* o4 = (const float4*)(op + (size_t)(4 * c4 + q) * NT);
                float4 a = o4[0], b = o4[1];
                acc[0] += ws[q] * a.x; acc[1] += ws[q] * a.y;
                acc[2] += ws[q] * a.z; acc[3] += ws[q] * a.w;
                acc[4] += ws[q] * b.x; acc[5] += ws[q] * b.y;
                acc[6] += ws[q] * b.z; acc[7] += ws[q] * b.w;
            }
        }
    }
    __shared__ float sh[8][NT];
#pragma unroll
    for (int t = 0; t < NT; t++) {
        float v = wred(acc[t]);
        if (lane == 0) sh[wid][t] = v;
    }
    __syncthreads();
    if (tid == 0) {
        float v[NT]; float sum = 0.f;
#pragma unroll
        for (int t = 0; t < NT; t++) {
            float s = 0.f;
#pragma unroll
            for (int w = 0; w < 8; w++) s += sh[w][t];
            float u = 0.7f * op[row * NT + t] + 0.3f * s + 0.01f * noise[row * NT + t];
            u = fmaxf(u, 0.01f);
            v[t] = u; sum += u;
        }
        float inv = 1.f / sum;
        int am = 0; float mx = v[0] * inv;
#pragma unroll
        for (int t = 1; t < NT; t++) {
            float u = v[t] * inv;
            if (u > mx) { mx = u; am = t; }
        }
        g_votes[row] = am;
        g_energy[row] = mx;
        atomicAdd(&g_counts[am], 1.f);
        atomicAdd(&g_cft[(row >> 9) * NT + am], 1.f);
    }
}

__global__ void k_gru(const float* __restrict__ hiddens)
{
    int i = blockIdx.x;
    float scale = 0.9f + 0.2f * g_energy[i];
    float t = g_tension[i] * (1.f / 1024.f);
    int vt = g_votes[i];
    int fa = i >> 9;
    const float4* gi = (const float4*)(g_gi + (size_t)i * G3);
    const float4* gh = (const float4*)(g_gh + (size_t)i * G3);
    const float4* wt = (const float4*)g_wt;
    const float4* hd = (const float4*)(hiddens + (size_t)i * 1024);
    float4* nh = (float4*)(g_nh + (size_t)i * HID);
    int j4 = threadIdx.x;
    float4 gir = gi[j4],        ghr = gh[j4];
    float4 giz = gi[j4 + 256],  ghz = gh[j4 + 256];
    float4 gin = gi[j4 + 512],  ghn = gh[j4 + 512];
    float4 wtr = wt[j4], wtz = wt[j4 + 256], wtn = wt[j4 + 512];
    float4 h = hd[j4];
    float4 o;
    {
        float r = 1.f / (1.f + expf(-(gir.x + t * wtr.x + ghr.x)));
        float z = 1.f / (1.f + expf(-(giz.x + t * wtz.x + ghz.x)));
        float n = tanhf(gin.x + t * wtn.x + r * ghn.x);
        o.x = fminf(fmaxf(((1.f - z) * n + z * h.x) * scale, -10.f), 10.f);
    }
    {
        float r = 1.f / (1.f + expf(-(gir.y + t * wtr.y + ghr.y)));
        float z = 1.f / (1.f + expf(-(giz.y + t * wtz.y + ghz.y)));
        float n = tanhf(gin.y + t * wtn.y + r * ghn.y);
        o.y = fminf(fmaxf(((1.f - z) * n + z * h.y) * scale, -10.f), 10.f);
    }
    {
        float r = 1.f / (1.f + expf(-(gir.z + t * wtr.z + ghr.z)));
        float z = 1.f / (1.f + expf(-(giz.z + t * wtz.z + ghz.z)));
        float n = tanhf(gin.z + t * wtn.z + r * ghn.z);
        o.z = fminf(fmaxf(((1.f - z) * n + z * h.z) * scale, -10.f), 10.f);
    }
    {
        float r = 1.f / (1.f + expf(-(gir.w + t * wtr.w + ghr.w)));
        float z = 1.f / (1.f + expf(-(giz.w + t * wtz.w + ghz.w)));
        float n = tanhf(gin.w + t * wtn.w + r * ghn.w);
        o.w = fminf(fmaxf(((1.f - z) * n + z * h.w) * scale, -10.f), 10.f);
    }
    nh[j4] = o;
    float* sums = g_fsum_ft + ((size_t)(fa * NT + vt)) * HID + 4 * j4;
    atomicAdd(sums + 0, o.x);
    atomicAdd(sums + 1, o.y);
    atomicAdd(sums + 2, o.z);
    atomicAdd(sums + 3, o.w);
}

__global__ void k_fblend()
{
    int c = blockIdx.x * 256 + threadIdx.x;
    float sums_t[NT];
#pragma unroll
    for (int t = 0; t < NT; t++) {
        float s = 0.f;
#pragma unroll
        for (int f = 0; f < NF; f++)
            s += g_fsum_ft[(size_t)(f * NT + t) * HID + c];
        sums_t[t] = s;
        g_sums[t * HID + c] = s;
    }
    float glob = 0.f;
#pragma unroll
    for (int f = 0; f < NF; f++) {
        float v = 0.f;
#pragma unroll
        for (int t = 0; t < NT; t++) {
            float raw = g_fsum_ft[(size_t)(f * NT + t) * HID + c];
            float cnt = g_counts[t];
            if (cnt >= 2.f)
                v += 0.85f * raw + 0.15f * g_cft[f * NT + t] * (sums_t[t] / fmaxf(cnt, 1.f));
            else
                v += raw;
        }
        g_fsums[f * HID + c] = v;
        glob += v;
    }
    g_glob[c] = glob * (1.f / 4096.f);
}

__global__ void k_final(float* __restrict__ out_nh, const int* __restrict__ step)
{
    int i = blockIdx.x;
    int f = i >> 9;
    int t = g_votes[i];
    float cnt = g_counts[t];
    bool ap = (cnt >= 2.f);
    float invc = 1.f / fmaxf(cnt, 1.f);
    bool dcz = (*step > 5) && ((i & 511) < 128);
    for (int jj = threadIdx.x; jj < HID; jj += 256) {
        float v = g_nh[(size_t)i * HID + jj];
        if (ap) v = 0.85f * v + 0.15f * g_sums[t * HID + jj] * invc;
        float fm = g_fsums[f * HID + jj] * (1.f / 512.f);
        v = 0.85f * v + 0.15f * fm;
        if (dcz) v = 0.85f * v + 0.15f * g_glob[jj];
        out_nh[(size_t)i * HID + jj] = v;
    }
}

__global__ void k_softmax(float* __restrict__ out_avg)
{
    __shared__ float sh[1024];
    int tid = threadIdx.x;
    float t4[4];
    float mx = -1e30f, av = 0.f;
#pragma unroll
    for (int q = 0; q < 4; q++) {
        t4[q] = g_tension[tid + q * 1024] * (1.f / 1024.f);
        mx = fmaxf(mx, t4[q]);
        av += t4[q];
    }
    sh[tid] = mx; __syncthreads();
    for (int o = 512; o > 0; o >>= 1) {
        if (tid < o) sh[tid] = fmaxf(sh[tid], sh[tid + o]);
        __syncthreads();
    }
    float M = sh[0]; __syncthreads();
    float sm = 0.f;
#pragma unroll
    for (int q = 0; q < 4; q++) {
        float e = expf(t4[q] - M);
        g_w[tid + q * 1024] = e;
        sm += e;
    }
    sh[tid] = sm; __syncthreads();
    for (int o = 512; o > 0; o >>= 1) {
        if (tid < o) sh[tid] += sh[tid + o];
        __syncthreads();
    }
    float inv = 1.f / sh[0]; __syncthreads();
#pragma unroll
    for (int q = 0; q < 4; q++) g_w[tid + q * 1024] *= inv;
    sh[tid] = av; __syncthreads();
    for (int o = 512; o > 0; o >>= 1) {
        if (tid < o) sh[tid] += sh[tid + o];
        __syncthreads();
    }
    if (tid == 0) out_avg[0] = sh[0] * (1.f / 4096.f);
}

__global__ void k_wA()
{
    int c = threadIdx.x;
    int r0 = blockIdx.x * 128;
    float acc = 0.f;
    for (int r = r0; r < r0 + 128; r++) {
        float w = g_w[r];
        float v = __half2float(g_a1g1_h[(size_t)r * 256 + c])
                + __half2float(g_a1g1_l[(size_t)r * 256 + c]);
        acc += w * v;
    }
    atomicAdd(&g_wa[c], acc);
}

__global__ void k_comb2()
{
    int jr = blockIdx.x * 8 + (threadIdx.x >> 5);
    int lane = threadIdx.x & 31;
    float s = 0.f;
    for (int m = lane; m < 256; m += 32) {
        float wv = __half2float(g_wc2_h[(size_t)jr * 256 + m])
                 + __half2float(g_wc2_l[(size_t)jr * 256 + m]);
        s += g_wa[m] * wv;
    }
    s = wred(s);
    if (lane == 0) g_combined[jr] = s + g_bconst[jr];
}

__global__ void k_pred(const float* __restrict__ Wo, const float* __restrict__ bo,
                       float* __restrict__ out_pred)
{
    int i = blockIdx.x * 8 + (threadIdx.x >> 5);
    int lane = threadIdx.x & 31;
    const float* row = Wo + (size_t)i * 1024;
    float s = 0.f;
    for (int jj = lane; jj < 1024; jj += 32) s += g_combined[jj] * row[jj];
    s = wred(s);
    if (lane == 0) out_pred[i] = s + bo[i];
}

// ---------------- launch ----------------
template <typename T>
static T* symp(const void* s)
{
    void* p = nullptr;
    cudaGetSymbolAddress(&p, s);
    return (T*)p;
}

#define SMEM_MI1 (2 * (2 * 64 * 128 + 2 * 128 * 128))    // 96 KB
#define SMEM_MI4 (2 * (2 * 256 * 128 + 2 * 128 * 128))   // 192 KB

extern "C" void kernel_launch(void* const* d_in, const int* in_sizes, int n_in,
                              void* d_out, int out_size)
{
    const float* x        = (const float*)d_in[0];
    const float* hiddens  = (const float*)d_in[1];
    const float* opinions = (const float*)d_in[2];
    const float* influence= (const float*)d_in[3];
    const float* noise    = (const float*)d_in[4];
    const float* Wa1 = (const float*)d_in[5];
    const float* ba1 = (const float*)d_in[6];
    const float* Wa2 = (const float*)d_in[7];
    const float* ba2 = (const float*)d_in[8];
    const float* Wg1 = (const float*)d_in[9];
    const float* bg1 = (const float*)d_in[10];
    const float* Wg2 = (const float*)d_in[11];
    const float* bg2 = (const float*)d_in[12];
    const float* W_ih = (const float*)d_in[13];
    const float* b_ih = (const float*)d_in[14];
    const float* W_hh = (const float*)d_in[15];
    const float* b_hh = (const float*)d_in[16];
    const float* Wo  = (const float*)d_in[17];
    const float* bo  = (const float*)d_in[18];
    const int*   step = (const int*)d_in[19];

    float* out = (float*)d_out;
    float* out_pred = out;
    float* out_avg  = out + 1024;
    float* out_nh   = out + 1025;

    hf* pHidH = symp<hf>(g_hid_h);  hf* pHidL = symp<hf>(g_hid_l);
    hf* pWihH = symp<hf>(g_wih_h);  hf* pWihL = symp<hf>(g_wih_l);
    hf* pWhhH = symp<hf>(g_whh_h);  hf* pWhhL = symp<hf>(g_whh_l);
    hf* pB1H  = symp<hf>(g_b1_h);   hf* pB1L  = symp<hf>(g_b1_l);
    hf* pWc2H = symp<hf>(g_wc2_h);  hf* pWc2L = symp<hf>(g_wc2_l);
    hf* pW2TH = symp<hf>(g_w2t_h);  hf* pW2TL = symp<hf>(g_w2t_l);
    hf* pMcH  = symp<hf>(g_mcat_h); hf* pMcL  = symp<hf>(g_mcat_l);
    hf* pAgH  = symp<hf>(g_a1g1_h); hf* pAgL  = symp<hf>(g_a1g1_l);
    float* pGi  = symp<float>(g_gi);
    float* pGh  = symp<float>(g_gh);
    float* pBias1 = symp<float>(g_bias1);
    float* pBconst= symp<float>(g_bconst);
    float* pVih = symp<float>(g_vih);

    static bool init_done = false;
    static bool use_streams = false;
    static cudaStream_t sM = nullptr, sV = nullptr, sG = nullptr;
    static cudaEvent_t ev0 = nullptr, evPC = nullptr, evM = nullptr, evBV = nullptr,
                       evV = nullptr, evG = nullptr, evT = nullptr, evP = nullptr;
    if (!init_done) {
        init_done = true;
        cudaFuncSetAttribute(gemm2<1, 4096, 3, 0, 3>,   // Mcat (3-prod)
                             cudaFuncAttributeMaxDynamicSharedMemorySize, SMEM_MI1);
        cudaFuncSetAttribute(gemm2<1, 4096, 1, 0, 3>,   // A1G1 (3-prod)
                             cudaFuncAttributeMaxDynamicSharedMemorySize, SMEM_MI1);
        cudaFuncSetAttribute(gemm2<4, 4096, 0, 0, 2>,   // gh (2-prod)
                             cudaFuncAttributeMaxDynamicSharedMemorySize, SMEM_MI4);
        cudaFuncSetAttribute(gemm2<4, 3072, 0, 2, 2>,   // gi | tension (2-prod)
                             cudaFuncAttributeMaxDynamicSharedMemorySize, SMEM_MI4);
        use_streams =
            (cudaStreamCreateWithFlags(&sM, cudaStreamNonBlocking) == cudaSuccess) &&
            (cudaStreamCreateWithFlags(&sV, cudaStreamNonBlocking) == cudaSuccess) &&
            (cudaStreamCreateWithFlags(&sG, cudaStreamNonBlocking) == cudaSuccess) &&
            (cudaEventCreateWithFlags(&ev0, cudaEventDisableTiming) == cudaSuccess) &&
            (cudaEventCreateWithFlags(&evPC, cudaEventDisableTiming) == cudaSuccess) &&
            (cudaEventCreateWithFlags(&evM, cudaEventDisableTiming) == cudaSuccess) &&
            (cudaEventCreateWithFlags(&evBV, cudaEventDisableTiming) == cudaSuccess) &&
            (cudaEventCreateWithFlags(&evV, cudaEventDisableTiming) == cudaSuccess) &&
            (cudaEventCreateWithFlags(&evG, cudaEventDisableTiming) == cudaSuccess) &&
            (cudaEventCreateWithFlags(&evT, cudaEventDisableTiming) == cudaSuccess) &&
            (cudaEventCreateWithFlags(&evP, cudaEventDisableTiming) == cudaSuccess);
    }

    cudaStream_t m = use_streams ? sM : (cudaStream_t)0;
    cudaStream_t vv = use_streams ? sV : (cudaStream_t)0;
    cudaStream_t gg = use_streams ? sG : (cudaStream_t)0;

    k_zero<<<256, 256>>>(ba2, bg2);

    if (use_streams) {
        cudaEventRecord(ev0, 0);
        cudaStreamWaitEvent(vv, ev0, 0);
        cudaStreamWaitEvent(m, ev0, 0);
    }
    k_vote<<<N_CELLS, 256, 0, vv>>>(influence, opinions, noise);
    if (use_streams) cudaEventRecord(evV, vv);

    // side stream: bias1, vih, prep_side, Mcat
    k_bias1<<<32, 256, 0, m>>>(Wa1, ba1, Wg1, bg1, x);
    k_vih<<<G3 / 8, 256, 0, m>>>(W_ih, b_ih);
    if (use_streams) cudaEventRecord(evBV, m);
    k_prep_side<<<6656, 256, 0, m>>>(W_ih, Wa2, Wg2);
    gemm2<1, 4096, 3, 0, 3><<<dim3(2, 48), 256, SMEM_MI1, m>>>(
        pWihH, pWihL, 1024,
        pW2TH, pW2TL, nullptr, nullptr,
        pMcH, pMcL, 256,
        nullptr, 0, nullptr, 0,
        1024, nullptr, nullptr);
    if (use_streams) cudaEventRecord(evM, m);

    // critical prep on stream 0 (float4)
    k_prep_crit<<<7424, 256>>>(hiddens, W_hh, Wa1, Wg1);
    if (use_streams) cudaEventRecord(evPC, 0);

    // gh GEMM on its own stream (2-prod fp16)
    if (use_streams) cudaStreamWaitEvent(gg, evPC, 0);
    gemm2<4, 4096, 0, 0, 2><<<dim3(24, 16), 256, SMEM_MI4, gg>>>(
        pHidH, pHidL, 1024,
        pWhhH, pWhhL, nullptr, nullptr,
        nullptr, nullptr, 0,
        pGh, G3, nullptr, 0,
        1024, b_hh, nullptr);
    if (use_streams) cudaEventRecord(evG, gg);

    // A1G1 GEMM on stream 0 (3-prod fp16)
    if (use_streams) cudaStreamWaitEvent(0, evBV, 0);
    gemm2<1, 4096, 1, 0, 3><<<dim3(2, 64), 256, SMEM_MI1>>>(
        pHidH, pHidL, 1024,
        pB1H, pB1L, nullptr, nullptr,
        pAgH, pAgL, 256,
        nullptr, 0, nullptr, 0,
        1024, pBias1, nullptr);

    // gi | tension GEMM on stream 0 (2-prod fp16)
    if (use_streams) cudaStreamWaitEvent(0, evM, 0);
    gemm2<4, 3072, 0, 2, 2><<<dim3(32, 16), 256, SMEM_MI4>>>(
        pAgH, pAgL, 256,
        pMcH, pMcL, pWc2H, pWc2L,
        nullptr, nullptr, 0,
        pGi, G3, nullptr, 0,
        256, pVih, pBconst);
    if (use_streams) { cudaEventRecord(evT, 0); cudaStreamWaitEvent(m, evT, 0); }

    // softmax -> pred chain on side stream
    k_softmax<<<1, 1024, 0, m>>>(out_avg);
    k_wA<<<32, 256, 0, m>>>();
    k_comb2<<<128, 256, 0, m>>>();
    k_pred<<<128, 256, 0, m>>>(Wo, bo, out_pred);
    if (use_streams) cudaEventRecord(evP, m);

    // GRU chain
    if (use_streams) { cudaStreamWaitEvent(0, evG, 0); cudaStreamWaitEvent(0, evV, 0); }
    k_gru<<<N_CELLS, 256>>>(hiddens);
    k_fblend<<<4, 256>>>();
    k_final<<<N_CELLS, 256>>>(out_nh, step);

    if (use_streams) cudaStreamWaitEvent(0, evP, 0);
}